// round 4
// baseline (speedup 1.0000x reference)
#include <cuda_runtime.h>

// ============================================================================
// EdgeAggregatorGATED round 4:
// Edge kernel restructured: warp-wide concatenated weights [Wkq|Wv] (128 cols,
// lane owns 4), R=8 edge blocking, smem-staged edge features (no mainloop
// SHFL), software-pipelined ea loads. Node kernel unchanged.
// ============================================================================

#define MAXN 51200
__device__ float g_kx[MAXN * 64];
__device__ float g_qx[MAXN * 64];
__device__ float g_vx[MAXN * 64];

typedef unsigned long long u64;

__device__ __forceinline__ u64 pack2(float x, float y) {
    u64 r;
    asm("mov.b64 %0, {%1,%2};" : "=l"(r) : "f"(x), "f"(y));
    return r;
}
__device__ __forceinline__ void unpack2(u64 v, float& x, float& y) {
    asm("mov.b64 {%0,%1}, %2;" : "=f"(x), "=f"(y) : "l"(v));
}
__device__ __forceinline__ void fma2(u64& d, u64 a, u64 b) {
    asm("fma.rn.f32x2 %0, %1, %2, %0;" : "+l"(d) : "l"(a), "l"(b));
}
__device__ __forceinline__ float fast_sigmoid(float s) {
    return __fdividef(1.0f, 1.0f + __expf(-s));
}

// ----------------------------------------------------------------------------
// Node kernel (unchanged from round 3): half-warp per 4-node group.
// part 0: kx,qx ; part 1: vx, skip+bias -> out.
// ----------------------------------------------------------------------------
__global__ __launch_bounds__(256, 2) void node_kernel(
    const float* __restrict__ x,
    const float* __restrict__ Wk, const float* __restrict__ Wq,
    const float* __restrict__ Wv, const float* __restrict__ Wskip,
    const float* __restrict__ bias,
    float* __restrict__ out, int N)
{
    __shared__ float WA[64][64];
    __shared__ float WB[64][64];
    const int tid = threadIdx.x;
    const int part = blockIdx.y;
    const float* srcA = (part == 0) ? Wk : Wv;
    const float* srcB = (part == 0) ? Wq : Wskip;
    for (int i = tid; i < 4096; i += 256) {
        (&WA[0][0])[i] = srcA[i];
        (&WB[0][0])[i] = srcB[i];
    }
    __syncthreads();

    const int hw = tid >> 4;
    const int l  = tid & 15;
    const int base = blockIdx.x * 128;
    float* outA = (part == 0) ? g_kx : g_vx;

    for (int it = 0; it < 2; ++it) {
        int n[4]; bool valid[4];
        float2 a0[4], a1[4];
        #pragma unroll
        for (int j = 0; j < 4; ++j) {
            n[j] = base + it * 64 + j * 16 + hw;
            valid[j] = (n[j] < N);
            int nc = valid[j] ? n[j] : 0;
            const float2* xr = (const float2*)(x + (size_t)nc * 64);
            a0[j] = xr[l];
            a1[j] = xr[16 + l];
        }

        u64 accA0[4], accA1[4], accB0[4], accB1[4];
        #pragma unroll
        for (int j = 0; j < 4; ++j) { accA0[j]=0; accA1[j]=0; accB0[j]=0; accB1[j]=0; }

        #pragma unroll
        for (int p = 0; p < 16; ++p) {
            ulonglong2 wa0 = *(const ulonglong2*)&WA[2 * p][4 * l];
            ulonglong2 wa1 = *(const ulonglong2*)&WA[2 * p + 1][4 * l];
            ulonglong2 wb0 = *(const ulonglong2*)&WB[2 * p][4 * l];
            ulonglong2 wb1 = *(const ulonglong2*)&WB[2 * p + 1][4 * l];
            #pragma unroll
            for (int j = 0; j < 4; ++j) {
                float ax = __shfl_sync(0xffffffffu, a0[j].x, p, 16);
                float ay = __shfl_sync(0xffffffffu, a0[j].y, p, 16);
                u64 ax2 = pack2(ax, ax), ay2 = pack2(ay, ay);
                fma2(accA0[j], ax2, wa0.x); fma2(accA1[j], ax2, wa0.y);
                fma2(accA0[j], ay2, wa1.x); fma2(accA1[j], ay2, wa1.y);
                fma2(accB0[j], ax2, wb0.x); fma2(accB1[j], ax2, wb0.y);
                fma2(accB0[j], ay2, wb1.x); fma2(accB1[j], ay2, wb1.y);
            }
        }
        #pragma unroll
        for (int p = 0; p < 16; ++p) {
            ulonglong2 wa0 = *(const ulonglong2*)&WA[32 + 2 * p][4 * l];
            ulonglong2 wa1 = *(const ulonglong2*)&WA[33 + 2 * p][4 * l];
            ulonglong2 wb0 = *(const ulonglong2*)&WB[32 + 2 * p][4 * l];
            ulonglong2 wb1 = *(const ulonglong2*)&WB[33 + 2 * p][4 * l];
            #pragma unroll
            for (int j = 0; j < 4; ++j) {
                float ax = __shfl_sync(0xffffffffu, a1[j].x, p, 16);
                float ay = __shfl_sync(0xffffffffu, a1[j].y, p, 16);
                u64 ax2 = pack2(ax, ax), ay2 = pack2(ay, ay);
                fma2(accA0[j], ax2, wa0.x); fma2(accA1[j], ax2, wa0.y);
                fma2(accA0[j], ay2, wa1.x); fma2(accA1[j], ay2, wa1.y);
                fma2(accB0[j], ax2, wb0.x); fma2(accB1[j], ax2, wb0.y);
                fma2(accB0[j], ay2, wb1.x); fma2(accB1[j], ay2, wb1.y);
            }
        }

        #pragma unroll
        for (int j = 0; j < 4; ++j) {
            if (!valid[j]) continue;
            float4 rA, rB;
            unpack2(accA0[j], rA.x, rA.y); unpack2(accA1[j], rA.z, rA.w);
            unpack2(accB0[j], rB.x, rB.y); unpack2(accB1[j], rB.z, rB.w);
            *(float4*)(outA + (size_t)n[j] * 64 + 4 * l) = rA;
            if (part == 0) {
                *(float4*)(g_qx + (size_t)n[j] * 64 + 4 * l) = rB;
            } else {
                float4 b4 = *(const float4*)(bias + 4 * l);
                rB.x += b4.x; rB.y += b4.y; rB.z += b4.z; rB.w += b4.w;
                *(float4*)(out + (size_t)n[j] * 64 + 4 * l) = rB;
            }
        }
    }
}

// ----------------------------------------------------------------------------
// Edge kernel v3: 256 threads = 8 warps. Warp processes 64 edges (8 iters x 8).
// Combined weights Wc[32][128] = [Wkq | Wv]. Lane l owns output cols 4l..4l+3
// (lanes 0-15: gate pre-activation, lanes 16-31: value).
// Edge features staged per-warp into smem; LDS.64 broadcast in mainloop.
// ----------------------------------------------------------------------------
#define EDGES_PER_WARP_ITER 8
#define ITERS_PER_WARP 8
#define EDGES_PER_BLOCK (8 * EDGES_PER_WARP_ITER * ITERS_PER_WARP)  // 512

__global__ __launch_bounds__(256) void edge_kernel(
    const float* __restrict__ ea,
    const int* __restrict__ srcArr, const int* __restrict__ dstArr,
    const float* __restrict__ Wk, const float* __restrict__ bk,
    const float* __restrict__ Wq, const float* __restrict__ bq,
    const float* __restrict__ Wv, const float* __restrict__ bv,
    float* __restrict__ out, int E)
{
    __shared__ float Wc[32][128];     // 16KB: cols 0-63 = Wk_e+Wq_e, 64-127 = Wv_e
    __shared__ float Bc[128];
    __shared__ float fbuf[8][256];    // 8KB: per-warp staged features [8 edges][32]

    const int tid  = threadIdx.x;
    const int w    = tid >> 5;
    const int lane = tid & 31;

    // Build combined weights/bias in smem.
    for (int i = tid; i < 4096; i += 256) {
        int r = i >> 7, c = i & 127;
        float v;
        if (c < 64) v = Wk[4096 + r * 64 + c] + Wq[4096 + r * 64 + c];
        else        v = Wv[4096 + r * 64 + (c - 64)];
        Wc[r][c] = v;
    }
    if (tid < 128) Bc[tid] = (tid < 64) ? (bk[tid] + bq[tid]) : bv[tid - 64];
    __syncthreads();

    const u64 b0 = pack2(Bc[4 * lane],     Bc[4 * lane + 1]);
    const u64 b1 = pack2(Bc[4 * lane + 2], Bc[4 * lane + 3]);

    const long wbase = (long)blockIdx.x * EDGES_PER_BLOCK + (long)w * (EDGES_PER_WARP_ITER * ITERS_PER_WARP);

    // Prefetch iter 0 features: 8 edges x 32 floats = 256 floats; lane takes 2 float4.
    long eb0 = wbase;
    long el0 = (eb0 + EDGES_PER_WARP_ITER <= E) ? eb0 : (E >= EDGES_PER_WARP_ITER ? E - EDGES_PER_WARP_ITER : 0);
    const float4* fp0 = (const float4*)(ea + el0 * 32);
    float4 r0 = fp0[2 * lane], r1 = fp0[2 * lane + 1];

    for (int t = 0; t < ITERS_PER_WARP; ++t) {
        long ebase = wbase + (long)t * EDGES_PER_WARP_ITER;
        if (ebase >= E) break;

        // Store staged features, then prefetch next iter.
        ((float4*)fbuf[w])[2 * lane] = r0;
        ((float4*)fbuf[w])[2 * lane + 1] = r1;
        __syncwarp();
        if (t + 1 < ITERS_PER_WARP) {
            long ebn = wbase + (long)(t + 1) * EDGES_PER_WARP_ITER;
            long eln = (ebn + EDGES_PER_WARP_ITER <= E) ? ebn : (E >= EDGES_PER_WARP_ITER ? E - EDGES_PER_WARP_ITER : 0);
            const float4* fpn = (const float4*)(ea + eln * 32);
            r0 = fpn[2 * lane]; r1 = fpn[2 * lane + 1];
        }

        u64 acc0[8], acc1[8];
        #pragma unroll
        for (int j = 0; j < 8; ++j) { acc0[j] = b0; acc1[j] = b1; }

        #pragma unroll
        for (int p = 0; p < 16; ++p) {
            ulonglong2 w0 = *(const ulonglong2*)&Wc[2 * p][4 * lane];
            ulonglong2 w1 = *(const ulonglong2*)&Wc[2 * p + 1][4 * lane];
            #pragma unroll
            for (int j = 0; j < 8; ++j) {
                float2 f = *(const float2*)&fbuf[w][j * 32 + 2 * p];  // broadcast
                u64 ax2 = pack2(f.x, f.x), ay2 = pack2(f.y, f.y);
                fma2(acc0[j], ax2, w0.x); fma2(acc1[j], ax2, w0.y);
                fma2(acc0[j], ay2, w1.x); fma2(acc1[j], ay2, w1.y);
            }
        }
        __syncwarp();  // done reading fbuf; safe to overwrite next iter

        // Epilogue: lanes 0-15 gate, lanes 16-31 value; shfl gate across.
        #pragma unroll
        for (int j = 0; j < 8; ++j) {
            long e = ebase + j;
            if (e >= E) break;
            int src = srcArr[e];
            int dst = dstArr[e];
            float4 a;
            unpack2(acc0[j], a.x, a.y); unpack2(acc1[j], a.z, a.w);
            float4 g;
            if (lane < 16) {
                float4 kd = *(const float4*)(g_kx + (size_t)dst * 64 + 4 * lane);
                float4 qs = *(const float4*)(g_qx + (size_t)src * 64 + 4 * lane);
                g.x = fast_sigmoid(a.x + kd.x + qs.x);
                g.y = fast_sigmoid(a.y + kd.y + qs.y);
                g.z = fast_sigmoid(a.z + kd.z + qs.z);
                g.w = fast_sigmoid(a.w + kd.w + qs.w);
            } else {
                float4 vs = *(const float4*)(g_vx + (size_t)src * 64 + 4 * lane - 64);
                a.x += vs.x; a.y += vs.y; a.z += vs.z; a.w += vs.w;
            }
            // lanes 16-31 receive gate from lane-16
            g.x = __shfl_sync(0xffffffffu, g.x, lane & 15);
            g.y = __shfl_sync(0xffffffffu, g.y, lane & 15);
            g.z = __shfl_sync(0xffffffffu, g.z, lane & 15);
            g.w = __shfl_sync(0xffffffffu, g.w, lane & 15);
            if (lane >= 16) {
                float m0 = g.x * a.x, m1 = g.y * a.y, m2 = g.z * a.z, m3 = g.w * a.w;
                float* p = out + (size_t)dst * 64 + 4 * lane - 64;
                asm volatile("red.global.add.v4.f32 [%0], {%1,%2,%3,%4};"
                             :: "l"(p), "f"(m0), "f"(m1), "f"(m2), "f"(m3) : "memory");
            }
        }
    }
}

// ----------------------------------------------------------------------------
// Launch. Inputs: x, edge_index, edge_attr, Wk, bk, Wq, bq, Wv, bv, Wskip, bias.
// ----------------------------------------------------------------------------
extern "C" void kernel_launch(void* const* d_in, const int* in_sizes, int n_in,
                              void* d_out, int out_size)
{
    const float* x     = (const float*)d_in[0];
    const int*   ei    = (const int*)d_in[1];
    const float* ea    = (const float*)d_in[2];
    const float* Wk    = (const float*)d_in[3];
    const float* bk    = (const float*)d_in[4];
    const float* Wq    = (const float*)d_in[5];
    const float* bq    = (const float*)d_in[6];
    const float* Wv    = (const float*)d_in[7];
    const float* bv    = (const float*)d_in[8];
    const float* Wskip = (const float*)d_in[9];
    const float* bias  = (const float*)d_in[10];
    float* out = (float*)d_out;

    int N = in_sizes[0] / 64;   // x is [N, 64]
    int E = in_sizes[2] / 32;   // edge_attr is [E, 32]

    dim3 ngrid((N + 127) / 128, 2);
    node_kernel<<<ngrid, 256>>>(x, Wk, Wq, Wv, Wskip, bias, out, N);

    int eblocks = (E + EDGES_PER_BLOCK - 1) / EDGES_PER_BLOCK;
    edge_kernel<<<eblocks, 256>>>(ea, ei, ei + E,
                                  Wk, bk, Wq, bq, Wv, bv, out, E);
}

// round 5
// speedup vs baseline: 1.2743x; 1.2743x over previous
#include <cuda_runtime.h>

// ============================================================================
// EdgeAggregatorGATED round 5:
// Edge kernel = register-tiled SGEMM (tile 128 edges x 128 cols [gate|value],
// micro-tile 8x8 per thread, gate+value cols co-resident per thread -> shfl-free
// epilogue). ea staged via cp.async into k-grouped transposed smem.
// Node kernel unchanged (proven).
// ============================================================================

#define MAXN 51200
__device__ float g_kx[MAXN * 64];
__device__ float g_qx[MAXN * 64];
__device__ float g_vx[MAXN * 64];

typedef unsigned long long u64;

__device__ __forceinline__ u64 pack2(float x, float y) {
    u64 r;
    asm("mov.b64 %0, {%1,%2};" : "=l"(r) : "f"(x), "f"(y));
    return r;
}
__device__ __forceinline__ void unpack2(u64 v, float& x, float& y) {
    asm("mov.b64 {%0,%1}, %2;" : "=f"(x), "=f"(y) : "l"(v));
}
__device__ __forceinline__ void fma2(u64& d, u64 a, u64 b) {
    asm("fma.rn.f32x2 %0, %1, %2, %0;" : "+l"(d) : "l"(a), "l"(b));
}
__device__ __forceinline__ float fast_sigmoid(float s) {
    return __fdividef(1.0f, 1.0f + __expf(-s));
}
__device__ __forceinline__ unsigned smem_u32(const void* p) {
    return (unsigned)__cvta_generic_to_shared(p);
}

// ----------------------------------------------------------------------------
// Node kernel (unchanged): half-warp per 4-node group.
// ----------------------------------------------------------------------------
__global__ __launch_bounds__(256, 2) void node_kernel(
    const float* __restrict__ x,
    const float* __restrict__ Wk, const float* __restrict__ Wq,
    const float* __restrict__ Wv, const float* __restrict__ Wskip,
    const float* __restrict__ bias,
    float* __restrict__ out, int N)
{
    __shared__ float WA[64][64];
    __shared__ float WB[64][64];
    const int tid = threadIdx.x;
    const int part = blockIdx.y;
    const float* srcA = (part == 0) ? Wk : Wv;
    const float* srcB = (part == 0) ? Wq : Wskip;
    for (int i = tid; i < 4096; i += 256) {
        (&WA[0][0])[i] = srcA[i];
        (&WB[0][0])[i] = srcB[i];
    }
    __syncthreads();

    const int hw = tid >> 4;
    const int l  = tid & 15;
    const int base = blockIdx.x * 128;
    float* outA = (part == 0) ? g_kx : g_vx;

    for (int it = 0; it < 2; ++it) {
        int n[4]; bool valid[4];
        float2 a0[4], a1[4];
        #pragma unroll
        for (int j = 0; j < 4; ++j) {
            n[j] = base + it * 64 + j * 16 + hw;
            valid[j] = (n[j] < N);
            int nc = valid[j] ? n[j] : 0;
            const float2* xr = (const float2*)(x + (size_t)nc * 64);
            a0[j] = xr[l];
            a1[j] = xr[16 + l];
        }

        u64 accA0[4], accA1[4], accB0[4], accB1[4];
        #pragma unroll
        for (int j = 0; j < 4; ++j) { accA0[j]=0; accA1[j]=0; accB0[j]=0; accB1[j]=0; }

        #pragma unroll
        for (int p = 0; p < 16; ++p) {
            ulonglong2 wa0 = *(const ulonglong2*)&WA[2 * p][4 * l];
            ulonglong2 wa1 = *(const ulonglong2*)&WA[2 * p + 1][4 * l];
            ulonglong2 wb0 = *(const ulonglong2*)&WB[2 * p][4 * l];
            ulonglong2 wb1 = *(const ulonglong2*)&WB[2 * p + 1][4 * l];
            #pragma unroll
            for (int j = 0; j < 4; ++j) {
                float ax = __shfl_sync(0xffffffffu, a0[j].x, p, 16);
                float ay = __shfl_sync(0xffffffffu, a0[j].y, p, 16);
                u64 ax2 = pack2(ax, ax), ay2 = pack2(ay, ay);
                fma2(accA0[j], ax2, wa0.x); fma2(accA1[j], ax2, wa0.y);
                fma2(accA0[j], ay2, wa1.x); fma2(accA1[j], ay2, wa1.y);
                fma2(accB0[j], ax2, wb0.x); fma2(accB1[j], ax2, wb0.y);
                fma2(accB0[j], ay2, wb1.x); fma2(accB1[j], ay2, wb1.y);
            }
        }
        #pragma unroll
        for (int p = 0; p < 16; ++p) {
            ulonglong2 wa0 = *(const ulonglong2*)&WA[32 + 2 * p][4 * l];
            ulonglong2 wa1 = *(const ulonglong2*)&WA[33 + 2 * p][4 * l];
            ulonglong2 wb0 = *(const ulonglong2*)&WB[32 + 2 * p][4 * l];
            ulonglong2 wb1 = *(const ulonglong2*)&WB[33 + 2 * p][4 * l];
            #pragma unroll
            for (int j = 0; j < 4; ++j) {
                float ax = __shfl_sync(0xffffffffu, a1[j].x, p, 16);
                float ay = __shfl_sync(0xffffffffu, a1[j].y, p, 16);
                u64 ax2 = pack2(ax, ax), ay2 = pack2(ay, ay);
                fma2(accA0[j], ax2, wa0.x); fma2(accA1[j], ax2, wa0.y);
                fma2(accA0[j], ay2, wa1.x); fma2(accA1[j], ay2, wa1.y);
                fma2(accB0[j], ax2, wb0.x); fma2(accB1[j], ax2, wb0.y);
                fma2(accB0[j], ay2, wb1.x); fma2(accB1[j], ay2, wb1.y);
            }
        }

        #pragma unroll
        for (int j = 0; j < 4; ++j) {
            if (!valid[j]) continue;
            float4 rA, rB;
            unpack2(accA0[j], rA.x, rA.y); unpack2(accA1[j], rA.z, rA.w);
            unpack2(accB0[j], rB.x, rB.y); unpack2(accB1[j], rB.z, rB.w);
            *(float4*)(outA + (size_t)n[j] * 64 + 4 * l) = rA;
            if (part == 0) {
                *(float4*)(g_qx + (size_t)n[j] * 64 + 4 * l) = rB;
            } else {
                float4 b4 = *(const float4*)(bias + 4 * l);
                rB.x += b4.x; rB.y += b4.y; rB.z += b4.z; rB.w += b4.w;
                *(float4*)(out + (size_t)n[j] * 64 + 4 * l) = rB;
            }
        }
    }
}

// ----------------------------------------------------------------------------
// Edge kernel v4: SGEMM-style tiling.
// CTA tile: 128 edges. Thread (ty,tx), ty=tid/16, tx=tid%16:
//   edges ty*8 .. ty*8+7 ; gate cols tx*4..+3 (Wc[:, tx*4]) ;
//   value cols tx*4..+3 (Wc[:, 64+tx*4]).
// smem: Wc[32][128]  ([Wkq | Wv]);  ea_t4[kk][e] float4 of k=4kk..4kk+3.
// ----------------------------------------------------------------------------
#define TILE_E 128

__global__ __launch_bounds__(256, 2) void edge_kernel(
    const float* __restrict__ ea,
    const int* __restrict__ srcArr, const int* __restrict__ dstArr,
    const float* __restrict__ Wk, const float* __restrict__ bk,
    const float* __restrict__ Wq, const float* __restrict__ bq,
    const float* __restrict__ Wv, const float* __restrict__ bv,
    float* __restrict__ out, int E)
{
    __shared__ float Wc[32][128];        // 16KB
    __shared__ float4 ea_t4[8][TILE_E];  // 16KB: [k-group][edge]
    __shared__ float Bc[128];

    const int tid = threadIdx.x;
    const int tx = tid & 15;
    const int ty = tid >> 4;
    const long ebase = (long)blockIdx.x * TILE_E;

    // --- Stage ea tile via cp.async: thread covers 4 consecutive 16B chunks.
    // chunk = e*8 + kk  (kk fastest -> contiguous global reads)
    {
        unsigned sbase = smem_u32(&ea_t4[0][0]);
        #pragma unroll
        for (int i = 0; i < 4; ++i) {
            int chunk = tid * 4 + i;          // 0..1023
            int e  = chunk >> 3;
            int kk = chunk & 7;
            long ge = ebase + e;
            if (ge >= E) ge = (long)E - 1;
            const float* gsrc = ea + ge * 32 + kk * 4;
            unsigned sdst = sbase + (unsigned)(kk * (TILE_E * 16) + e * 16);
            asm volatile("cp.async.cg.shared.global [%0], [%1], 16;"
                         :: "r"(sdst), "l"(gsrc));
        }
        asm volatile("cp.async.commit_group;");
    }

    // --- Build combined weights/bias (overlaps with cp.async in flight).
    for (int i = tid; i < 4096; i += 256) {
        int r = i >> 7, c = i & 127;
        float v;
        if (c < 64) v = Wk[4096 + r * 64 + c] + Wq[4096 + r * 64 + c];
        else        v = Wv[4096 + r * 64 + (c - 64)];
        Wc[r][c] = v;
    }
    if (tid < 128) Bc[tid] = (tid < 64) ? (bk[tid] + bq[tid]) : bv[tid - 64];

    asm volatile("cp.async.wait_group 0;");
    __syncthreads();

    const u64 bg0 = pack2(Bc[4 * tx],     Bc[4 * tx + 1]);
    const u64 bg1 = pack2(Bc[4 * tx + 2], Bc[4 * tx + 3]);
    const u64 bv0 = pack2(Bc[64 + 4 * tx],     Bc[64 + 4 * tx + 1]);
    const u64 bv1 = pack2(Bc[64 + 4 * tx + 2], Bc[64 + 4 * tx + 3]);

    // Accumulators: 8 edges x (gate 2 u64 + value 2 u64)
    u64 ag0[8], ag1[8], av0[8], av1[8];
    #pragma unroll
    for (int j = 0; j < 8; ++j) { ag0[j]=bg0; ag1[j]=bg1; av0[j]=bv0; av1[j]=bv1; }

    #pragma unroll
    for (int kk = 0; kk < 8; ++kk) {
        // B-frags for 4 k's: gate + value, 2 u64 each
        ulonglong2 wg[4], wv[4];
        #pragma unroll
        for (int k = 0; k < 4; ++k) {
            wg[k] = *(const ulonglong2*)&Wc[4 * kk + k][4 * tx];
            wv[k] = *(const ulonglong2*)&Wc[4 * kk + k][64 + 4 * tx];
        }
        #pragma unroll
        for (int j = 0; j < 8; ++j) {
            float4 a4 = ea_t4[kk][ty * 8 + j];   // 4 k-values of edge j (broadcast)
            u64 a0 = pack2(a4.x, a4.x);
            u64 a1 = pack2(a4.y, a4.y);
            u64 a2 = pack2(a4.z, a4.z);
            u64 a3 = pack2(a4.w, a4.w);
            fma2(ag0[j], a0, wg[0].x); fma2(ag1[j], a0, wg[0].y);
            fma2(av0[j], a0, wv[0].x); fma2(av1[j], a0, wv[0].y);
            fma2(ag0[j], a1, wg[1].x); fma2(ag1[j], a1, wg[1].y);
            fma2(av0[j], a1, wv[1].x); fma2(av1[j], a1, wv[1].y);
            fma2(ag0[j], a2, wg[2].x); fma2(ag1[j], a2, wg[2].y);
            fma2(av0[j], a2, wv[2].x); fma2(av1[j], a2, wv[2].y);
            fma2(ag0[j], a3, wg[3].x); fma2(ag1[j], a3, wg[3].y);
            fma2(av0[j], a3, wv[3].x); fma2(av1[j], a3, wv[3].y);
        }
    }

    // --- Epilogue: gather, gate, scatter-add. No cross-thread exchange needed.
    #pragma unroll
    for (int j = 0; j < 8; ++j) {
        long e = ebase + ty * 8 + j;
        if (e >= E) break;
        int src = srcArr[e];
        int dst = dstArr[e];
        float4 kd = *(const float4*)(g_kx + (size_t)dst * 64 + 4 * tx);
        float4 qs = *(const float4*)(g_qx + (size_t)src * 64 + 4 * tx);
        float4 vs = *(const float4*)(g_vx + (size_t)src * 64 + 4 * tx);
        float g0c, g1c, g2c, g3c, v0c, v1c, v2c, v3c;
        unpack2(ag0[j], g0c, g1c); unpack2(ag1[j], g2c, g3c);
        unpack2(av0[j], v0c, v1c); unpack2(av1[j], v2c, v3c);
        float m0 = fast_sigmoid(g0c + kd.x + qs.x) * (v0c + vs.x);
        float m1 = fast_sigmoid(g1c + kd.y + qs.y) * (v1c + vs.y);
        float m2 = fast_sigmoid(g2c + kd.z + qs.z) * (v2c + vs.z);
        float m3 = fast_sigmoid(g3c + kd.w + qs.w) * (v3c + vs.w);
        float* p = out + (size_t)dst * 64 + 4 * tx;
        asm volatile("red.global.add.v4.f32 [%0], {%1,%2,%3,%4};"
                     :: "l"(p), "f"(m0), "f"(m1), "f"(m2), "f"(m3) : "memory");
    }
}

// ----------------------------------------------------------------------------
// Launch. Inputs: x, edge_index, edge_attr, Wk, bk, Wq, bq, Wv, bv, Wskip, bias.
// ----------------------------------------------------------------------------
extern "C" void kernel_launch(void* const* d_in, const int* in_sizes, int n_in,
                              void* d_out, int out_size)
{
    const float* x     = (const float*)d_in[0];
    const int*   ei    = (const int*)d_in[1];
    const float* ea    = (const float*)d_in[2];
    const float* Wk    = (const float*)d_in[3];
    const float* bk    = (const float*)d_in[4];
    const float* Wq    = (const float*)d_in[5];
    const float* bq    = (const float*)d_in[6];
    const float* Wv    = (const float*)d_in[7];
    const float* bv    = (const float*)d_in[8];
    const float* Wskip = (const float*)d_in[9];
    const float* bias  = (const float*)d_in[10];
    float* out = (float*)d_out;

    int N = in_sizes[0] / 64;   // x is [N, 64]
    int E = in_sizes[2] / 32;   // edge_attr is [E, 32]

    dim3 ngrid((N + 127) / 128, 2);
    node_kernel<<<ngrid, 256>>>(x, Wk, Wq, Wv, Wskip, bias, out, N);

    int eblocks = (E + TILE_E - 1) / TILE_E;
    edge_kernel<<<eblocks, 256>>>(ea, ei, ei + E,
                                  Wk, bk, Wq, bq, Wv, bv, out, E);
}

// round 7
// speedup vs baseline: 1.4146x; 1.1101x over previous
#include <cuda_runtime.h>

// ============================================================================
// EdgeAggregatorGATED round 7:
// Round-6 design (persistent-CTA SGEMM edge kernel, double-buffered cp.async
// staging) with the smem overflow fixed: bias array removed from smem (loaded
// to registers from global), static smem = exactly 48KB.
// ============================================================================

#define MAXN 51200
__device__ float g_kx[MAXN * 64];
__device__ float g_qx[MAXN * 64];
__device__ float g_vx[MAXN * 64];

typedef unsigned long long u64;

__device__ __forceinline__ u64 pack2(float x, float y) {
    u64 r;
    asm("mov.b64 %0, {%1,%2};" : "=l"(r) : "f"(x), "f"(y));
    return r;
}
__device__ __forceinline__ void unpack2(u64 v, float& x, float& y) {
    asm("mov.b64 {%0,%1}, %2;" : "=f"(x), "=f"(y) : "l"(v));
}
__device__ __forceinline__ void fma2(u64& d, u64 a, u64 b) {
    asm("fma.rn.f32x2 %0, %1, %2, %0;" : "+l"(d) : "l"(a), "l"(b));
}
__device__ __forceinline__ float fast_sigmoid(float s) {
    return __fdividef(1.0f, 1.0f + __expf(-s));
}
__device__ __forceinline__ unsigned smem_u32(const void* p) {
    return (unsigned)__cvta_generic_to_shared(p);
}

// ----------------------------------------------------------------------------
// Node kernel (unchanged): half-warp per 4-node group.
// ----------------------------------------------------------------------------
__global__ __launch_bounds__(256, 2) void node_kernel(
    const float* __restrict__ x,
    const float* __restrict__ Wk, const float* __restrict__ Wq,
    const float* __restrict__ Wv, const float* __restrict__ Wskip,
    const float* __restrict__ bias,
    float* __restrict__ out, int N)
{
    __shared__ float WA[64][64];
    __shared__ float WB[64][64];
    const int tid = threadIdx.x;
    const int part = blockIdx.y;
    const float* srcA = (part == 0) ? Wk : Wv;
    const float* srcB = (part == 0) ? Wq : Wskip;
    for (int i = tid; i < 4096; i += 256) {
        (&WA[0][0])[i] = srcA[i];
        (&WB[0][0])[i] = srcB[i];
    }
    __syncthreads();

    const int hw = tid >> 4;
    const int l  = tid & 15;
    const int base = blockIdx.x * 128;
    float* outA = (part == 0) ? g_kx : g_vx;

    for (int it = 0; it < 2; ++it) {
        int n[4]; bool valid[4];
        float2 a0[4], a1[4];
        #pragma unroll
        for (int j = 0; j < 4; ++j) {
            n[j] = base + it * 64 + j * 16 + hw;
            valid[j] = (n[j] < N);
            int nc = valid[j] ? n[j] : 0;
            const float2* xr = (const float2*)(x + (size_t)nc * 64);
            a0[j] = xr[l];
            a1[j] = xr[16 + l];
        }

        u64 accA0[4], accA1[4], accB0[4], accB1[4];
        #pragma unroll
        for (int j = 0; j < 4; ++j) { accA0[j]=0; accA1[j]=0; accB0[j]=0; accB1[j]=0; }

        #pragma unroll
        for (int p = 0; p < 16; ++p) {
            ulonglong2 wa0 = *(const ulonglong2*)&WA[2 * p][4 * l];
            ulonglong2 wa1 = *(const ulonglong2*)&WA[2 * p + 1][4 * l];
            ulonglong2 wb0 = *(const ulonglong2*)&WB[2 * p][4 * l];
            ulonglong2 wb1 = *(const ulonglong2*)&WB[2 * p + 1][4 * l];
            #pragma unroll
            for (int j = 0; j < 4; ++j) {
                float ax = __shfl_sync(0xffffffffu, a0[j].x, p, 16);
                float ay = __shfl_sync(0xffffffffu, a0[j].y, p, 16);
                u64 ax2 = pack2(ax, ax), ay2 = pack2(ay, ay);
                fma2(accA0[j], ax2, wa0.x); fma2(accA1[j], ax2, wa0.y);
                fma2(accA0[j], ay2, wa1.x); fma2(accA1[j], ay2, wa1.y);
                fma2(accB0[j], ax2, wb0.x); fma2(accB1[j], ax2, wb0.y);
                fma2(accB0[j], ay2, wb1.x); fma2(accB1[j], ay2, wb1.y);
            }
        }
        #pragma unroll
        for (int p = 0; p < 16; ++p) {
            ulonglong2 wa0 = *(const ulonglong2*)&WA[32 + 2 * p][4 * l];
            ulonglong2 wa1 = *(const ulonglong2*)&WA[33 + 2 * p][4 * l];
            ulonglong2 wb0 = *(const ulonglong2*)&WB[32 + 2 * p][4 * l];
            ulonglong2 wb1 = *(const ulonglong2*)&WB[33 + 2 * p][4 * l];
            #pragma unroll
            for (int j = 0; j < 4; ++j) {
                float ax = __shfl_sync(0xffffffffu, a1[j].x, p, 16);
                float ay = __shfl_sync(0xffffffffu, a1[j].y, p, 16);
                u64 ax2 = pack2(ax, ax), ay2 = pack2(ay, ay);
                fma2(accA0[j], ax2, wa0.x); fma2(accA1[j], ax2, wa0.y);
                fma2(accA0[j], ay2, wa1.x); fma2(accA1[j], ay2, wa1.y);
                fma2(accB0[j], ax2, wb0.x); fma2(accB1[j], ax2, wb0.y);
                fma2(accB0[j], ay2, wb1.x); fma2(accB1[j], ay2, wb1.y);
            }
        }

        #pragma unroll
        for (int j = 0; j < 4; ++j) {
            if (!valid[j]) continue;
            float4 rA, rB;
            unpack2(accA0[j], rA.x, rA.y); unpack2(accA1[j], rA.z, rA.w);
            unpack2(accB0[j], rB.x, rB.y); unpack2(accB1[j], rB.z, rB.w);
            *(float4*)(outA + (size_t)n[j] * 64 + 4 * l) = rA;
            if (part == 0) {
                *(float4*)(g_qx + (size_t)n[j] * 64 + 4 * l) = rB;
            } else {
                float4 b4 = *(const float4*)(bias + 4 * l);
                rB.x += b4.x; rB.y += b4.y; rB.z += b4.z; rB.w += b4.w;
                *(float4*)(out + (size_t)n[j] * 64 + 4 * l) = rB;
            }
        }
    }
}

// ----------------------------------------------------------------------------
// Edge kernel v6: persistent CTAs, double-buffered feature staging.
// smem = Wc (16KB) + ea_t4 (32KB) = exactly 48KB. Biases live in registers.
// ----------------------------------------------------------------------------
#define TILE_E 128

__device__ __forceinline__ void stage_tile(
    const float* __restrict__ ea, long ebase, int E,
    unsigned sbase, int tid)
{
    #pragma unroll
    for (int i = 0; i < 4; ++i) {
        int chunk = tid * 4 + i;          // 0..1023
        int e  = chunk >> 3;
        int kk = chunk & 7;
        long ge = ebase + e;
        if (ge >= E) ge = (long)E - 1;
        const float* gsrc = ea + ge * 32 + kk * 4;
        unsigned sdst = sbase + (unsigned)(kk * (TILE_E * 16) + e * 16);
        asm volatile("cp.async.cg.shared.global [%0], [%1], 16;"
                     :: "r"(sdst), "l"(gsrc));
    }
    asm volatile("cp.async.commit_group;");
}

__global__ __launch_bounds__(256, 2) void edge_kernel(
    const float* __restrict__ ea,
    const int* __restrict__ srcArr, const int* __restrict__ dstArr,
    const float* __restrict__ Wk, const float* __restrict__ bk,
    const float* __restrict__ Wq, const float* __restrict__ bq,
    const float* __restrict__ Wv, const float* __restrict__ bv,
    float* __restrict__ out, int E, int numTiles)
{
    __shared__ float Wc[32][128];            // 16KB
    __shared__ float4 ea_t4[2][8][TILE_E];   // 32KB double-buffered

    const int tid = threadIdx.x;
    const int tx = tid & 15;
    const int ty = tid >> 4;

    // --- Prologue (once per CTA): combined weights into smem.
    for (int i = tid; i < 4096; i += 256) {
        int r = i >> 7, c = i & 127;
        float v;
        if (c < 64) v = Wk[4096 + r * 64 + c] + Wq[4096 + r * 64 + c];
        else        v = Wv[4096 + r * 64 + (c - 64)];
        Wc[r][c] = v;
    }

    // Biases directly to registers (uniform per tx -> L1 broadcast).
    float4 bk4 = *(const float4*)(bk + 4 * tx);
    float4 bq4 = *(const float4*)(bq + 4 * tx);
    float4 bv4 = *(const float4*)(bv + 4 * tx);
    const u64 bg0 = pack2(bk4.x + bq4.x, bk4.y + bq4.y);
    const u64 bg1 = pack2(bk4.z + bq4.z, bk4.w + bq4.w);
    const u64 bv0 = pack2(bv4.x, bv4.y);
    const u64 bv1 = pack2(bv4.z, bv4.w);

    // Prefetch first tile into buffer 0.
    long tile0 = blockIdx.x;
    if (tile0 < numTiles)
        stage_tile(ea, tile0 * TILE_E, E, smem_u32(&ea_t4[0][0][0]), tid);
    __syncthreads();

    int idx = 0;
    for (long tile = blockIdx.x; tile < numTiles; tile += gridDim.x, ++idx) {
        const int cur = idx & 1;
        const long ebase = tile * TILE_E;
        const long ntile = tile + gridDim.x;

        // Prefetch next tile into the other buffer, then wait for current.
        if (ntile < numTiles) {
            stage_tile(ea, ntile * TILE_E, E, smem_u32(&ea_t4[cur ^ 1][0][0]), tid);
            asm volatile("cp.async.wait_group 1;");
        } else {
            asm volatile("cp.async.wait_group 0;");
        }
        __syncthreads();

        u64 ag0[8], ag1[8], av0[8], av1[8];
        #pragma unroll
        for (int j = 0; j < 8; ++j) { ag0[j]=bg0; ag1[j]=bg1; av0[j]=bv0; av1[j]=bv1; }

        #pragma unroll
        for (int kk = 0; kk < 8; ++kk) {
            ulonglong2 wg[4], wv[4];
            #pragma unroll
            for (int k = 0; k < 4; ++k) {
                wg[k] = *(const ulonglong2*)&Wc[4 * kk + k][4 * tx];
                wv[k] = *(const ulonglong2*)&Wc[4 * kk + k][64 + 4 * tx];
            }
            #pragma unroll
            for (int j = 0; j < 8; ++j) {
                float4 a4 = ea_t4[cur][kk][ty * 8 + j];  // broadcast
                u64 a0 = pack2(a4.x, a4.x);
                u64 a1 = pack2(a4.y, a4.y);
                u64 a2 = pack2(a4.z, a4.z);
                u64 a3 = pack2(a4.w, a4.w);
                fma2(ag0[j], a0, wg[0].x); fma2(ag1[j], a0, wg[0].y);
                fma2(av0[j], a0, wv[0].x); fma2(av1[j], a0, wv[0].y);
                fma2(ag0[j], a1, wg[1].x); fma2(ag1[j], a1, wg[1].y);
                fma2(av0[j], a1, wv[1].x); fma2(av1[j], a1, wv[1].y);
                fma2(ag0[j], a2, wg[2].x); fma2(ag1[j], a2, wg[2].y);
                fma2(av0[j], a2, wv[2].x); fma2(av1[j], a2, wv[2].y);
                fma2(ag0[j], a3, wg[3].x); fma2(ag1[j], a3, wg[3].y);
                fma2(av0[j], a3, wv[3].x); fma2(av1[j], a3, wv[3].y);
            }
        }

        // Epilogue: gather node terms, gate, scatter-add. Shfl-free.
        #pragma unroll
        for (int j = 0; j < 8; ++j) {
            long e = ebase + ty * 8 + j;
            if (e >= E) break;
            int src = srcArr[e];
            int dst = dstArr[e];
            float4 kd = *(const float4*)(g_kx + (size_t)dst * 64 + 4 * tx);
            float4 qs = *(const float4*)(g_qx + (size_t)src * 64 + 4 * tx);
            float4 vs = *(const float4*)(g_vx + (size_t)src * 64 + 4 * tx);
            float g0c, g1c, g2c, g3c, v0c, v1c, v2c, v3c;
            unpack2(ag0[j], g0c, g1c); unpack2(ag1[j], g2c, g3c);
            unpack2(av0[j], v0c, v1c); unpack2(av1[j], v2c, v3c);
            float m0 = fast_sigmoid(g0c + kd.x + qs.x) * (v0c + vs.x);
            float m1 = fast_sigmoid(g1c + kd.y + qs.y) * (v1c + vs.y);
            float m2 = fast_sigmoid(g2c + kd.z + qs.z) * (v2c + vs.z);
            float m3 = fast_sigmoid(g3c + kd.w + qs.w) * (v3c + vs.w);
            float* p = out + (size_t)dst * 64 + 4 * tx;
            asm volatile("red.global.add.v4.f32 [%0], {%1,%2,%3,%4};"
                         :: "l"(p), "f"(m0), "f"(m1), "f"(m2), "f"(m3) : "memory");
        }
        __syncthreads();  // all reads of ea_t4[cur] done before it is re-staged
    }
}

// ----------------------------------------------------------------------------
// Launch. Inputs: x, edge_index, edge_attr, Wk, bk, Wq, bq, Wv, bv, Wskip, bias.
// ----------------------------------------------------------------------------
extern "C" void kernel_launch(void* const* d_in, const int* in_sizes, int n_in,
                              void* d_out, int out_size)
{
    const float* x     = (const float*)d_in[0];
    const int*   ei    = (const int*)d_in[1];
    const float* ea    = (const float*)d_in[2];
    const float* Wk    = (const float*)d_in[3];
    const float* bk    = (const float*)d_in[4];
    const float* Wq    = (const float*)d_in[5];
    const float* bq    = (const float*)d_in[6];
    const float* Wv    = (const float*)d_in[7];
    const float* bv    = (const float*)d_in[8];
    const float* Wskip = (const float*)d_in[9];
    const float* bias  = (const float*)d_in[10];
    float* out = (float*)d_out;

    int N = in_sizes[0] / 64;   // x is [N, 64]
    int E = in_sizes[2] / 32;   // edge_attr is [E, 32]

    dim3 ngrid((N + 127) / 128, 2);
    node_kernel<<<ngrid, 256>>>(x, Wk, Wq, Wv, Wskip, bias, out, N);

    int numTiles = (E + TILE_E - 1) / TILE_E;
    int grid = numTiles < 296 ? numTiles : 296;  // 2 CTAs per SM, persistent
    edge_kernel<<<grid, 256>>>(ea, ei, ei + E,
                               Wk, bk, Wq, bq, Wv, bv, out, E, numTiles);
}

// round 8
// speedup vs baseline: 1.4742x; 1.0421x over previous
#include <cuda_runtime.h>

// ============================================================================
// EdgeAggregatorGATED round 8:
// R7 persistent-CTA SGEMM edge kernel + epilogue latency hiding:
//   - __syncthreads moved to after mainloop (epilogue decoupled)
//   - tile indices batched via int4 loads
//   - depth-2 software pipeline on kd/qs/vs gathers
// Node kernel unchanged.
// ============================================================================

#define MAXN 51200
__device__ float g_kx[MAXN * 64];
__device__ float g_qx[MAXN * 64];
__device__ float g_vx[MAXN * 64];

typedef unsigned long long u64;

__device__ __forceinline__ u64 pack2(float x, float y) {
    u64 r;
    asm("mov.b64 %0, {%1,%2};" : "=l"(r) : "f"(x), "f"(y));
    return r;
}
__device__ __forceinline__ void unpack2(u64 v, float& x, float& y) {
    asm("mov.b64 {%0,%1}, %2;" : "=f"(x), "=f"(y) : "l"(v));
}
__device__ __forceinline__ void fma2(u64& d, u64 a, u64 b) {
    asm("fma.rn.f32x2 %0, %1, %2, %0;" : "+l"(d) : "l"(a), "l"(b));
}
__device__ __forceinline__ float fast_sigmoid(float s) {
    return __fdividef(1.0f, 1.0f + __expf(-s));
}
__device__ __forceinline__ unsigned smem_u32(const void* p) {
    return (unsigned)__cvta_generic_to_shared(p);
}

// ----------------------------------------------------------------------------
// Node kernel (unchanged): half-warp per 4-node group.
// ----------------------------------------------------------------------------
__global__ __launch_bounds__(256, 2) void node_kernel(
    const float* __restrict__ x,
    const float* __restrict__ Wk, const float* __restrict__ Wq,
    const float* __restrict__ Wv, const float* __restrict__ Wskip,
    const float* __restrict__ bias,
    float* __restrict__ out, int N)
{
    __shared__ float WA[64][64];
    __shared__ float WB[64][64];
    const int tid = threadIdx.x;
    const int part = blockIdx.y;
    const float* srcA = (part == 0) ? Wk : Wv;
    const float* srcB = (part == 0) ? Wq : Wskip;
    for (int i = tid; i < 4096; i += 256) {
        (&WA[0][0])[i] = srcA[i];
        (&WB[0][0])[i] = srcB[i];
    }
    __syncthreads();

    const int hw = tid >> 4;
    const int l  = tid & 15;
    const int base = blockIdx.x * 128;
    float* outA = (part == 0) ? g_kx : g_vx;

    for (int it = 0; it < 2; ++it) {
        int n[4]; bool valid[4];
        float2 a0[4], a1[4];
        #pragma unroll
        for (int j = 0; j < 4; ++j) {
            n[j] = base + it * 64 + j * 16 + hw;
            valid[j] = (n[j] < N);
            int nc = valid[j] ? n[j] : 0;
            const float2* xr = (const float2*)(x + (size_t)nc * 64);
            a0[j] = xr[l];
            a1[j] = xr[16 + l];
        }

        u64 accA0[4], accA1[4], accB0[4], accB1[4];
        #pragma unroll
        for (int j = 0; j < 4; ++j) { accA0[j]=0; accA1[j]=0; accB0[j]=0; accB1[j]=0; }

        #pragma unroll
        for (int p = 0; p < 16; ++p) {
            ulonglong2 wa0 = *(const ulonglong2*)&WA[2 * p][4 * l];
            ulonglong2 wa1 = *(const ulonglong2*)&WA[2 * p + 1][4 * l];
            ulonglong2 wb0 = *(const ulonglong2*)&WB[2 * p][4 * l];
            ulonglong2 wb1 = *(const ulonglong2*)&WB[2 * p + 1][4 * l];
            #pragma unroll
            for (int j = 0; j < 4; ++j) {
                float ax = __shfl_sync(0xffffffffu, a0[j].x, p, 16);
                float ay = __shfl_sync(0xffffffffu, a0[j].y, p, 16);
                u64 ax2 = pack2(ax, ax), ay2 = pack2(ay, ay);
                fma2(accA0[j], ax2, wa0.x); fma2(accA1[j], ax2, wa0.y);
                fma2(accA0[j], ay2, wa1.x); fma2(accA1[j], ay2, wa1.y);
                fma2(accB0[j], ax2, wb0.x); fma2(accB1[j], ax2, wb0.y);
                fma2(accB0[j], ay2, wb1.x); fma2(accB1[j], ay2, wb1.y);
            }
        }
        #pragma unroll
        for (int p = 0; p < 16; ++p) {
            ulonglong2 wa0 = *(const ulonglong2*)&WA[32 + 2 * p][4 * l];
            ulonglong2 wa1 = *(const ulonglong2*)&WA[33 + 2 * p][4 * l];
            ulonglong2 wb0 = *(const ulonglong2*)&WB[32 + 2 * p][4 * l];
            ulonglong2 wb1 = *(const ulonglong2*)&WB[33 + 2 * p][4 * l];
            #pragma unroll
            for (int j = 0; j < 4; ++j) {
                float ax = __shfl_sync(0xffffffffu, a1[j].x, p, 16);
                float ay = __shfl_sync(0xffffffffu, a1[j].y, p, 16);
                u64 ax2 = pack2(ax, ax), ay2 = pack2(ay, ay);
                fma2(accA0[j], ax2, wa0.x); fma2(accA1[j], ax2, wa0.y);
                fma2(accA0[j], ay2, wa1.x); fma2(accA1[j], ay2, wa1.y);
                fma2(accB0[j], ax2, wb0.x); fma2(accB1[j], ax2, wb0.y);
                fma2(accB0[j], ay2, wb1.x); fma2(accB1[j], ay2, wb1.y);
            }
        }

        #pragma unroll
        for (int j = 0; j < 4; ++j) {
            if (!valid[j]) continue;
            float4 rA, rB;
            unpack2(accA0[j], rA.x, rA.y); unpack2(accA1[j], rA.z, rA.w);
            unpack2(accB0[j], rB.x, rB.y); unpack2(accB1[j], rB.z, rB.w);
            *(float4*)(outA + (size_t)n[j] * 64 + 4 * l) = rA;
            if (part == 0) {
                *(float4*)(g_qx + (size_t)n[j] * 64 + 4 * l) = rB;
            } else {
                float4 b4 = *(const float4*)(bias + 4 * l);
                rB.x += b4.x; rB.y += b4.y; rB.z += b4.z; rB.w += b4.w;
                *(float4*)(out + (size_t)n[j] * 64 + 4 * l) = rB;
            }
        }
    }
}

// ----------------------------------------------------------------------------
// Edge kernel v7: persistent CTAs, double-buffered staging, pipelined epilogue.
// ----------------------------------------------------------------------------
#define TILE_E 128

__device__ __forceinline__ void stage_tile(
    const float* __restrict__ ea, long ebase, int E,
    unsigned sbase, int tid)
{
    #pragma unroll
    for (int i = 0; i < 4; ++i) {
        int chunk = tid * 4 + i;          // 0..1023
        int e  = chunk >> 3;
        int kk = chunk & 7;
        long ge = ebase + e;
        if (ge >= E) ge = (long)E - 1;
        const float* gsrc = ea + ge * 32 + kk * 4;
        unsigned sdst = sbase + (unsigned)(kk * (TILE_E * 16) + e * 16);
        asm volatile("cp.async.cg.shared.global [%0], [%1], 16;"
                     :: "r"(sdst), "l"(gsrc));
    }
    asm volatile("cp.async.commit_group;");
}

__global__ __launch_bounds__(256, 2) void edge_kernel(
    const float* __restrict__ ea,
    const int* __restrict__ srcArr, const int* __restrict__ dstArr,
    const float* __restrict__ Wk, const float* __restrict__ bk,
    const float* __restrict__ Wq, const float* __restrict__ bq,
    const float* __restrict__ Wv, const float* __restrict__ bv,
    float* __restrict__ out, int E, int numTiles)
{
    __shared__ float Wc[32][128];            // 16KB
    __shared__ float4 ea_t4[2][8][TILE_E];   // 32KB double-buffered

    const int tid = threadIdx.x;
    const int tx = tid & 15;
    const int ty = tid >> 4;

    // --- Prologue (once per CTA): combined weights into smem.
    for (int i = tid; i < 4096; i += 256) {
        int r = i >> 7, c = i & 127;
        float v;
        if (c < 64) v = Wk[4096 + r * 64 + c] + Wq[4096 + r * 64 + c];
        else        v = Wv[4096 + r * 64 + (c - 64)];
        Wc[r][c] = v;
    }

    // Biases directly to registers.
    float4 bk4 = *(const float4*)(bk + 4 * tx);
    float4 bq4 = *(const float4*)(bq + 4 * tx);
    float4 bv4 = *(const float4*)(bv + 4 * tx);
    const u64 bg0 = pack2(bk4.x + bq4.x, bk4.y + bq4.y);
    const u64 bg1 = pack2(bk4.z + bq4.z, bk4.w + bq4.w);
    const u64 bv0 = pack2(bv4.x, bv4.y);
    const u64 bv1 = pack2(bv4.z, bv4.w);

    // Prefetch first tile into buffer 0.
    long tile0 = blockIdx.x;
    if (tile0 < numTiles)
        stage_tile(ea, tile0 * TILE_E, E, smem_u32(&ea_t4[0][0][0]), tid);
    __syncthreads();

    int idx = 0;
    for (long tile = blockIdx.x; tile < numTiles; tile += gridDim.x, ++idx) {
        const int cur = idx & 1;
        const long ebase = tile * TILE_E;
        const long ntile = tile + gridDim.x;

        // Prefetch next tile into the other buffer, then wait for current.
        if (ntile < numTiles) {
            stage_tile(ea, ntile * TILE_E, E, smem_u32(&ea_t4[cur ^ 1][0][0]), tid);
            asm volatile("cp.async.wait_group 1;");
        } else {
            asm volatile("cp.async.wait_group 0;");
        }
        __syncthreads();

        u64 ag0[8], ag1[8], av0[8], av1[8];
        #pragma unroll
        for (int j = 0; j < 8; ++j) { ag0[j]=bg0; ag1[j]=bg1; av0[j]=bv0; av1[j]=bv1; }

        #pragma unroll
        for (int kk = 0; kk < 8; ++kk) {
            ulonglong2 wg[4], wv[4];
            #pragma unroll
            for (int k = 0; k < 4; ++k) {
                wg[k] = *(const ulonglong2*)&Wc[4 * kk + k][4 * tx];
                wv[k] = *(const ulonglong2*)&Wc[4 * kk + k][64 + 4 * tx];
            }
            #pragma unroll
            for (int j = 0; j < 8; ++j) {
                float4 a4 = ea_t4[cur][kk][ty * 8 + j];  // broadcast
                u64 a0 = pack2(a4.x, a4.x);
                u64 a1 = pack2(a4.y, a4.y);
                u64 a2 = pack2(a4.z, a4.z);
                u64 a3 = pack2(a4.w, a4.w);
                fma2(ag0[j], a0, wg[0].x); fma2(ag1[j], a0, wg[0].y);
                fma2(av0[j], a0, wv[0].x); fma2(av1[j], a0, wv[0].y);
                fma2(ag0[j], a1, wg[1].x); fma2(ag1[j], a1, wg[1].y);
                fma2(av0[j], a1, wv[1].x); fma2(av1[j], a1, wv[1].y);
                fma2(ag0[j], a2, wg[2].x); fma2(ag1[j], a2, wg[2].y);
                fma2(av0[j], a2, wv[2].x); fma2(av1[j], a2, wv[2].y);
                fma2(ag0[j], a3, wg[3].x); fma2(ag1[j], a3, wg[3].y);
                fma2(av0[j], a3, wv[3].x); fma2(av1[j], a3, wv[3].y);
            }
        }
        // All reads of ea_t4[cur] done; epilogue uses no smem, so sync HERE.
        // Next iteration's stage_tile may then safely overwrite buffer `cur`.
        __syncthreads();

        // ---- Epilogue: batched indices + depth-2 pipelined gathers ----
        const long e0 = ebase + (long)ty * 8;
        int srcs[8], dsts[8];
        if (e0 + 8 <= E) {
            int4 s03 = *(const int4*)(srcArr + e0);
            int4 s47 = *(const int4*)(srcArr + e0 + 4);
            int4 d03 = *(const int4*)(dstArr + e0);
            int4 d47 = *(const int4*)(dstArr + e0 + 4);
            srcs[0]=s03.x; srcs[1]=s03.y; srcs[2]=s03.z; srcs[3]=s03.w;
            srcs[4]=s47.x; srcs[5]=s47.y; srcs[6]=s47.z; srcs[7]=s47.w;
            dsts[0]=d03.x; dsts[1]=d03.y; dsts[2]=d03.z; dsts[3]=d03.w;
            dsts[4]=d47.x; dsts[5]=d47.y; dsts[6]=d47.z; dsts[7]=d47.w;
        } else {
            #pragma unroll
            for (int j = 0; j < 8; ++j) {
                long e = e0 + j;
                long ec = (e < E) ? e : (long)(E - 1);
                srcs[j] = srcArr[ec];
                dsts[j] = dstArr[ec];
            }
        }

        float4 kdb[2], qsb[2], vsb[2];
        #pragma unroll
        for (int j = 0; j < 2; ++j) {
            kdb[j] = *(const float4*)(g_kx + (size_t)dsts[j] * 64 + 4 * tx);
            qsb[j] = *(const float4*)(g_qx + (size_t)srcs[j] * 64 + 4 * tx);
            vsb[j] = *(const float4*)(g_vx + (size_t)srcs[j] * 64 + 4 * tx);
        }

        #pragma unroll
        for (int j = 0; j < 8; ++j) {
            float4 kd = kdb[j & 1], qs = qsb[j & 1], vs = vsb[j & 1];
            if (j + 2 < 8) {
                kdb[j & 1] = *(const float4*)(g_kx + (size_t)dsts[j + 2] * 64 + 4 * tx);
                qsb[j & 1] = *(const float4*)(g_qx + (size_t)srcs[j + 2] * 64 + 4 * tx);
                vsb[j & 1] = *(const float4*)(g_vx + (size_t)srcs[j + 2] * 64 + 4 * tx);
            }
            float g0c, g1c, g2c, g3c, v0c, v1c, v2c, v3c;
            unpack2(ag0[j], g0c, g1c); unpack2(ag1[j], g2c, g3c);
            unpack2(av0[j], v0c, v1c); unpack2(av1[j], v2c, v3c);
            float m0 = fast_sigmoid(g0c + kd.x + qs.x) * (v0c + vs.x);
            float m1 = fast_sigmoid(g1c + kd.y + qs.y) * (v1c + vs.y);
            float m2 = fast_sigmoid(g2c + kd.z + qs.z) * (v2c + vs.z);
            float m3 = fast_sigmoid(g3c + kd.w + qs.w) * (v3c + vs.w);
            if (e0 + j < E) {
                float* p = out + (size_t)dsts[j] * 64 + 4 * tx;
                asm volatile("red.global.add.v4.f32 [%0], {%1,%2,%3,%4};"
                             :: "l"(p), "f"(m0), "f"(m1), "f"(m2), "f"(m3) : "memory");
            }
        }
    }
}

// ----------------------------------------------------------------------------
// Launch. Inputs: x, edge_index, edge_attr, Wk, bk, Wq, bq, Wv, bv, Wskip, bias.
// ----------------------------------------------------------------------------
extern "C" void kernel_launch(void* const* d_in, const int* in_sizes, int n_in,
                              void* d_out, int out_size)
{
    const float* x     = (const float*)d_in[0];
    const int*   ei    = (const int*)d_in[1];
    const float* ea    = (const float*)d_in[2];
    const float* Wk    = (const float*)d_in[3];
    const float* bk    = (const float*)d_in[4];
    const float* Wq    = (const float*)d_in[5];
    const float* bq    = (const float*)d_in[6];
    const float* Wv    = (const float*)d_in[7];
    const float* bv    = (const float*)d_in[8];
    const float* Wskip = (const float*)d_in[9];
    const float* bias  = (const float*)d_in[10];
    float* out = (float*)d_out;

    int N = in_sizes[0] / 64;   // x is [N, 64]
    int E = in_sizes[2] / 32;   // edge_attr is [E, 32]

    dim3 ngrid((N + 127) / 128, 2);
    node_kernel<<<ngrid, 256>>>(x, Wk, Wq, Wv, Wskip, bias, out, N);

    int numTiles = (E + TILE_E - 1) / TILE_E;
    int grid = numTiles < 296 ? numTiles : 296;  // 2 CTAs per SM, persistent
    edge_kernel<<<grid, 256>>>(ea, ei, ei + E,
                               Wk, bk, Wq, bq, Wv, bv, out, E, numTiles);
}

// round 9
// speedup vs baseline: 1.5274x; 1.0361x over previous
#include <cuda_runtime.h>

// ============================================================================
// EdgeAggregatorGATED round 9:
// Occupancy push: edge micro-tile 8->4 edges/thread (32 acc regs), tile 64
// edges, smem 32KB, __launch_bounds__(256,3) -> 3 CTAs/SM (24 warps, was 16).
// Persistent CTAs + double-buffered cp.async staging + pipelined epilogue kept.
// Node kernel unchanged.
// ============================================================================

#define MAXN 51200
__device__ float g_kx[MAXN * 64];
__device__ float g_qx[MAXN * 64];
__device__ float g_vx[MAXN * 64];

typedef unsigned long long u64;

__device__ __forceinline__ u64 pack2(float x, float y) {
    u64 r;
    asm("mov.b64 %0, {%1,%2};" : "=l"(r) : "f"(x), "f"(y));
    return r;
}
__device__ __forceinline__ void unpack2(u64 v, float& x, float& y) {
    asm("mov.b64 {%0,%1}, %2;" : "=f"(x), "=f"(y) : "l"(v));
}
__device__ __forceinline__ void fma2(u64& d, u64 a, u64 b) {
    asm("fma.rn.f32x2 %0, %1, %2, %0;" : "+l"(d) : "l"(a), "l"(b));
}
__device__ __forceinline__ float fast_sigmoid(float s) {
    return __fdividef(1.0f, 1.0f + __expf(-s));
}
__device__ __forceinline__ unsigned smem_u32(const void* p) {
    return (unsigned)__cvta_generic_to_shared(p);
}

// ----------------------------------------------------------------------------
// Node kernel (unchanged): half-warp per 4-node group.
// ----------------------------------------------------------------------------
__global__ __launch_bounds__(256, 2) void node_kernel(
    const float* __restrict__ x,
    const float* __restrict__ Wk, const float* __restrict__ Wq,
    const float* __restrict__ Wv, const float* __restrict__ Wskip,
    const float* __restrict__ bias,
    float* __restrict__ out, int N)
{
    __shared__ float WA[64][64];
    __shared__ float WB[64][64];
    const int tid = threadIdx.x;
    const int part = blockIdx.y;
    const float* srcA = (part == 0) ? Wk : Wv;
    const float* srcB = (part == 0) ? Wq : Wskip;
    for (int i = tid; i < 4096; i += 256) {
        (&WA[0][0])[i] = srcA[i];
        (&WB[0][0])[i] = srcB[i];
    }
    __syncthreads();

    const int hw = tid >> 4;
    const int l  = tid & 15;
    const int base = blockIdx.x * 128;
    float* outA = (part == 0) ? g_kx : g_vx;

    for (int it = 0; it < 2; ++it) {
        int n[4]; bool valid[4];
        float2 a0[4], a1[4];
        #pragma unroll
        for (int j = 0; j < 4; ++j) {
            n[j] = base + it * 64 + j * 16 + hw;
            valid[j] = (n[j] < N);
            int nc = valid[j] ? n[j] : 0;
            const float2* xr = (const float2*)(x + (size_t)nc * 64);
            a0[j] = xr[l];
            a1[j] = xr[16 + l];
        }

        u64 accA0[4], accA1[4], accB0[4], accB1[4];
        #pragma unroll
        for (int j = 0; j < 4; ++j) { accA0[j]=0; accA1[j]=0; accB0[j]=0; accB1[j]=0; }

        #pragma unroll
        for (int p = 0; p < 16; ++p) {
            ulonglong2 wa0 = *(const ulonglong2*)&WA[2 * p][4 * l];
            ulonglong2 wa1 = *(const ulonglong2*)&WA[2 * p + 1][4 * l];
            ulonglong2 wb0 = *(const ulonglong2*)&WB[2 * p][4 * l];
            ulonglong2 wb1 = *(const ulonglong2*)&WB[2 * p + 1][4 * l];
            #pragma unroll
            for (int j = 0; j < 4; ++j) {
                float ax = __shfl_sync(0xffffffffu, a0[j].x, p, 16);
                float ay = __shfl_sync(0xffffffffu, a0[j].y, p, 16);
                u64 ax2 = pack2(ax, ax), ay2 = pack2(ay, ay);
                fma2(accA0[j], ax2, wa0.x); fma2(accA1[j], ax2, wa0.y);
                fma2(accA0[j], ay2, wa1.x); fma2(accA1[j], ay2, wa1.y);
                fma2(accB0[j], ax2, wb0.x); fma2(accB1[j], ax2, wb0.y);
                fma2(accB0[j], ay2, wb1.x); fma2(accB1[j], ay2, wb1.y);
            }
        }
        #pragma unroll
        for (int p = 0; p < 16; ++p) {
            ulonglong2 wa0 = *(const ulonglong2*)&WA[32 + 2 * p][4 * l];
            ulonglong2 wa1 = *(const ulonglong2*)&WA[33 + 2 * p][4 * l];
            ulonglong2 wb0 = *(const ulonglong2*)&WB[32 + 2 * p][4 * l];
            ulonglong2 wb1 = *(const ulonglong2*)&WB[33 + 2 * p][4 * l];
            #pragma unroll
            for (int j = 0; j < 4; ++j) {
                float ax = __shfl_sync(0xffffffffu, a1[j].x, p, 16);
                float ay = __shfl_sync(0xffffffffu, a1[j].y, p, 16);
                u64 ax2 = pack2(ax, ax), ay2 = pack2(ay, ay);
                fma2(accA0[j], ax2, wa0.x); fma2(accA1[j], ax2, wa0.y);
                fma2(accA0[j], ay2, wa1.x); fma2(accA1[j], ay2, wa1.y);
                fma2(accB0[j], ax2, wb0.x); fma2(accB1[j], ax2, wb0.y);
                fma2(accB0[j], ay2, wb1.x); fma2(accB1[j], ay2, wb1.y);
            }
        }

        #pragma unroll
        for (int j = 0; j < 4; ++j) {
            if (!valid[j]) continue;
            float4 rA, rB;
            unpack2(accA0[j], rA.x, rA.y); unpack2(accA1[j], rA.z, rA.w);
            unpack2(accB0[j], rB.x, rB.y); unpack2(accB1[j], rB.z, rB.w);
            *(float4*)(outA + (size_t)n[j] * 64 + 4 * l) = rA;
            if (part == 0) {
                *(float4*)(g_qx + (size_t)n[j] * 64 + 4 * l) = rB;
            } else {
                float4 b4 = *(const float4*)(bias + 4 * l);
                rB.x += b4.x; rB.y += b4.y; rB.z += b4.z; rB.w += b4.w;
                *(float4*)(out + (size_t)n[j] * 64 + 4 * l) = rB;
            }
        }
    }
}

// ----------------------------------------------------------------------------
// Edge kernel v8: 4-edge micro-tile, 64-edge tile, 3 CTAs/SM.
// Thread (ty,tx), ty=tid/16 (0..15), tx=tid%16: edges ty*4..+3,
// gate cols tx*4..+3 and value cols 64+tx*4..+3.
// ----------------------------------------------------------------------------
#define TILE_E 64

__device__ __forceinline__ void stage_tile(
    const float* __restrict__ ea, long ebase, int E,
    unsigned sbase, int tid)
{
    #pragma unroll
    for (int i = 0; i < 2; ++i) {
        int chunk = tid * 2 + i;          // 0..511
        int e  = chunk >> 3;
        int kk = chunk & 7;
        long ge = ebase + e;
        if (ge >= E) ge = (long)E - 1;
        const float* gsrc = ea + ge * 32 + kk * 4;
        unsigned sdst = sbase + (unsigned)(kk * (TILE_E * 16) + e * 16);
        asm volatile("cp.async.cg.shared.global [%0], [%1], 16;"
                     :: "r"(sdst), "l"(gsrc));
    }
    asm volatile("cp.async.commit_group;");
}

__global__ __launch_bounds__(256, 3) void edge_kernel(
    const float* __restrict__ ea,
    const int* __restrict__ srcArr, const int* __restrict__ dstArr,
    const float* __restrict__ Wk, const float* __restrict__ bk,
    const float* __restrict__ Wq, const float* __restrict__ bq,
    const float* __restrict__ Wv, const float* __restrict__ bv,
    float* __restrict__ out, int E, int numTiles)
{
    __shared__ float Wc[32][128];            // 16KB
    __shared__ float4 ea_t4[2][8][TILE_E];   // 16KB double-buffered

    const int tid = threadIdx.x;
    const int tx = tid & 15;
    const int ty = tid >> 4;

    // --- Prologue (once per CTA): combined weights into smem.
    for (int i = tid; i < 4096; i += 256) {
        int r = i >> 7, c = i & 127;
        float v;
        if (c < 64) v = Wk[4096 + r * 64 + c] + Wq[4096 + r * 64 + c];
        else        v = Wv[4096 + r * 64 + (c - 64)];
        Wc[r][c] = v;
    }

    // Biases to registers.
    float4 bk4 = *(const float4*)(bk + 4 * tx);
    float4 bq4 = *(const float4*)(bq + 4 * tx);
    float4 bv4 = *(const float4*)(bv + 4 * tx);
    const u64 bg0 = pack2(bk4.x + bq4.x, bk4.y + bq4.y);
    const u64 bg1 = pack2(bk4.z + bq4.z, bk4.w + bq4.w);
    const u64 bb0 = pack2(bv4.x, bv4.y);
    const u64 bb1 = pack2(bv4.z, bv4.w);

    long tile0 = blockIdx.x;
    if (tile0 < numTiles)
        stage_tile(ea, tile0 * TILE_E, E, smem_u32(&ea_t4[0][0][0]), tid);
    __syncthreads();

    int idx = 0;
    for (long tile = blockIdx.x; tile < numTiles; tile += gridDim.x, ++idx) {
        const int cur = idx & 1;
        const long ebase = tile * TILE_E;
        const long ntile = tile + gridDim.x;

        if (ntile < numTiles) {
            stage_tile(ea, ntile * TILE_E, E, smem_u32(&ea_t4[cur ^ 1][0][0]), tid);
            asm volatile("cp.async.wait_group 1;");
        } else {
            asm volatile("cp.async.wait_group 0;");
        }
        __syncthreads();

        u64 ag0[4], ag1[4], av0[4], av1[4];
        #pragma unroll
        for (int j = 0; j < 4; ++j) { ag0[j]=bg0; ag1[j]=bg1; av0[j]=bb0; av1[j]=bb1; }

        #pragma unroll
        for (int kk = 0; kk < 8; ++kk) {
            float4 a4[4];
            #pragma unroll
            for (int j = 0; j < 4; ++j) a4[j] = ea_t4[cur][kk][ty * 4 + j];

            // Rows in 2-row halves to limit transient register pressure.
            #pragma unroll
            for (int h = 0; h < 2; ++h) {
                ulonglong2 wg0 = *(const ulonglong2*)&Wc[4 * kk + 2 * h][4 * tx];
                ulonglong2 wg1 = *(const ulonglong2*)&Wc[4 * kk + 2 * h + 1][4 * tx];
                ulonglong2 wv0 = *(const ulonglong2*)&Wc[4 * kk + 2 * h][64 + 4 * tx];
                ulonglong2 wv1 = *(const ulonglong2*)&Wc[4 * kk + 2 * h + 1][64 + 4 * tx];
                #pragma unroll
                for (int j = 0; j < 4; ++j) {
                    float f0 = h ? a4[j].z : a4[j].x;
                    float f1 = h ? a4[j].w : a4[j].y;
                    u64 a0 = pack2(f0, f0);
                    u64 a1 = pack2(f1, f1);
                    fma2(ag0[j], a0, wg0.x); fma2(ag1[j], a0, wg0.y);
                    fma2(av0[j], a0, wv0.x); fma2(av1[j], a0, wv0.y);
                    fma2(ag0[j], a1, wg1.x); fma2(ag1[j], a1, wg1.y);
                    fma2(av0[j], a1, wv1.x); fma2(av1[j], a1, wv1.y);
                }
            }
        }
        // Last smem reads of this buffer done; epilogue is smem-free.
        __syncthreads();

        // ---- Epilogue: batched indices + depth-2 pipelined gathers ----
        const long e0 = ebase + (long)ty * 4;
        int srcs[4], dsts[4];
        if (e0 + 4 <= E) {
            int4 s = *(const int4*)(srcArr + e0);
            int4 d = *(const int4*)(dstArr + e0);
            srcs[0]=s.x; srcs[1]=s.y; srcs[2]=s.z; srcs[3]=s.w;
            dsts[0]=d.x; dsts[1]=d.y; dsts[2]=d.z; dsts[3]=d.w;
        } else {
            #pragma unroll
            for (int j = 0; j < 4; ++j) {
                long e = e0 + j;
                long ec = (e < E) ? e : (long)(E - 1);
                srcs[j] = srcArr[ec];
                dsts[j] = dstArr[ec];
            }
        }

        float4 kdb[2], qsb[2], vsb[2];
        #pragma unroll
        for (int j = 0; j < 2; ++j) {
            kdb[j] = *(const float4*)(g_kx + (size_t)dsts[j] * 64 + 4 * tx);
            qsb[j] = *(const float4*)(g_qx + (size_t)srcs[j] * 64 + 4 * tx);
            vsb[j] = *(const float4*)(g_vx + (size_t)srcs[j] * 64 + 4 * tx);
        }

        #pragma unroll
        for (int j = 0; j < 4; ++j) {
            float4 kd = kdb[j & 1], qs = qsb[j & 1], vs = vsb[j & 1];
            if (j + 2 < 4) {
                kdb[j & 1] = *(const float4*)(g_kx + (size_t)dsts[j + 2] * 64 + 4 * tx);
                qsb[j & 1] = *(const float4*)(g_qx + (size_t)srcs[j + 2] * 64 + 4 * tx);
                vsb[j & 1] = *(const float4*)(g_vx + (size_t)srcs[j + 2] * 64 + 4 * tx);
            }
            float g0c, g1c, g2c, g3c, v0c, v1c, v2c, v3c;
            unpack2(ag0[j], g0c, g1c); unpack2(ag1[j], g2c, g3c);
            unpack2(av0[j], v0c, v1c); unpack2(av1[j], v2c, v3c);
            float m0 = fast_sigmoid(g0c + kd.x + qs.x) * (v0c + vs.x);
            float m1 = fast_sigmoid(g1c + kd.y + qs.y) * (v1c + vs.y);
            float m2 = fast_sigmoid(g2c + kd.z + qs.z) * (v2c + vs.z);
            float m3 = fast_sigmoid(g3c + kd.w + qs.w) * (v3c + vs.w);
            if (e0 + j < E) {
                float* p = out + (size_t)dsts[j] * 64 + 4 * tx;
                asm volatile("red.global.add.v4.f32 [%0], {%1,%2,%3,%4};"
                             :: "l"(p), "f"(m0), "f"(m1), "f"(m2), "f"(m3) : "memory");
            }
        }
    }
}

// ----------------------------------------------------------------------------
// Launch. Inputs: x, edge_index, edge_attr, Wk, bk, Wq, bq, Wv, bv, Wskip, bias.
// ----------------------------------------------------------------------------
extern "C" void kernel_launch(void* const* d_in, const int* in_sizes, int n_in,
                              void* d_out, int out_size)
{
    const float* x     = (const float*)d_in[0];
    const int*   ei    = (const int*)d_in[1];
    const float* ea    = (const float*)d_in[2];
    const float* Wk    = (const float*)d_in[3];
    const float* bk    = (const float*)d_in[4];
    const float* Wq    = (const float*)d_in[5];
    const float* bq    = (const float*)d_in[6];
    const float* Wv    = (const float*)d_in[7];
    const float* bv    = (const float*)d_in[8];
    const float* Wskip = (const float*)d_in[9];
    const float* bias  = (const float*)d_in[10];
    float* out = (float*)d_out;

    int N = in_sizes[0] / 64;   // x is [N, 64]
    int E = in_sizes[2] / 32;   // edge_attr is [E, 32]

    dim3 ngrid((N + 127) / 128, 2);
    node_kernel<<<ngrid, 256>>>(x, Wk, Wq, Wv, Wskip, bias, out, N);

    int numTiles = (E + TILE_E - 1) / TILE_E;
    int grid = numTiles < 444 ? numTiles : 444;  // 3 CTAs per SM, persistent
    edge_kernel<<<grid, 256>>>(ea, ei, ei + E,
                               Wk, bk, Wq, bq, Wv, bv, out, E, numTiles);
}

// round 11
// speedup vs baseline: 1.7909x; 1.1725x over previous
#include <cuda_runtime.h>
#include <cuda_bf16.h>
#include <cstdint>

// ============================================================================
// EdgeAggregatorGATED round 11: mma.sync tensor-core edge GEMM.
// tcgen05 unavailable (harness emits compute_100 PTX, no 'a' features), so the
// edge linears run on mma.sync.m16n8k16 bf16 with split-bf16 (hi+lo, 3
// products) for ~fp32 accuracy. A fragments built directly in registers
// (stager == consumer), B pre-packed once into fragment layout (16KB smem).
// Epilogue: fragment-layout drain, float2 gathers, RED.64. Node kernel keeps
// bias folding (kx += bk+bq, vx += bv).
// ============================================================================

#define MAXN 51200
__device__ float g_kx[MAXN * 64];
__device__ float g_qx[MAXN * 64];
__device__ float g_vx[MAXN * 64];
__device__ uint4 g_Bpack[1024];   // [nt16][kt2][lane32] = {b0h,b1h,b0l,b1l}, 16KB

typedef unsigned long long u64;

__device__ __forceinline__ u64 pack2(float x, float y) {
    u64 r; asm("mov.b64 %0, {%1,%2};" : "=l"(r) : "f"(x), "f"(y)); return r;
}
__device__ __forceinline__ void unpack2(u64 v, float& x, float& y) {
    asm("mov.b64 {%0,%1}, %2;" : "=f"(x), "=f"(y) : "l"(v));
}
__device__ __forceinline__ void fma2(u64& d, u64 a, u64 b) {
    asm("fma.rn.f32x2 %0, %1, %2, %0;" : "+l"(d) : "l"(a), "l"(b));
}
__device__ __forceinline__ float fast_sigmoid(float s) {
    return __fdividef(1.0f, 1.0f + __expf(-s));
}
__device__ __forceinline__ unsigned smem_u32(const void* p) {
    return (unsigned)__cvta_generic_to_shared(p);
}

// bf16x2 pack: a -> bits[15:0], b -> bits[31:16]
__device__ __forceinline__ uint32_t bf2(float a, float b) {
    uint32_t r; asm("cvt.rn.bf16x2.f32 %0, %1, %2;" : "=r"(r) : "f"(b), "f"(a));
    return r;
}
// recover the two bf16 values as floats (bf16 bits << 16 == float bits)
__device__ __forceinline__ float2 bf2_back(uint32_t h) {
    return make_float2(__uint_as_float(h << 16), __uint_as_float(h & 0xffff0000u));
}
// split pair (a,b) into hi bf16x2 and lo (residual) bf16x2
__device__ __forceinline__ void split2(float a, float b, uint32_t& hi, uint32_t& lo) {
    hi = bf2(a, b);
    float2 hb = bf2_back(hi);
    lo = bf2(a - hb.x, b - hb.y);
}

__device__ __forceinline__ void mma_bf16(float c[4], const uint32_t a[4],
                                         uint32_t b0, uint32_t b1) {
    asm volatile(
        "mma.sync.aligned.m16n8k16.row.col.f32.bf16.bf16.f32 "
        "{%0,%1,%2,%3}, {%4,%5,%6,%7}, {%8,%9}, {%0,%1,%2,%3};"
        : "+f"(c[0]), "+f"(c[1]), "+f"(c[2]), "+f"(c[3])
        : "r"(a[0]), "r"(a[1]), "r"(a[2]), "r"(a[3]), "r"(b0), "r"(b1));
}

// ----------------------------------------------------------------------------
// bpack: B = [Wkq_e | Wv_e] as [n=128][k=32] split-bf16, mma-fragment layout.
// slot s = (nt*2+kt)*32+lane ; lane: n = nt*8+(lane>>2), k0 = kt*16+2*(lane&3).
// values: {k0,k0+1} -> b0, {k0+8,k0+9} -> b1.
// ----------------------------------------------------------------------------
__global__ void bpack_kernel(const float* __restrict__ Wk,
                             const float* __restrict__ Wq,
                             const float* __restrict__ Wv)
{
    int t = threadIdx.x;  // 256 threads
    #pragma unroll
    for (int i = 0; i < 4; ++i) {
        int s = t * 4 + i;
        int nt = s >> 6;
        int kt = (s >> 5) & 1;
        int lane = s & 31;
        int n = nt * 8 + (lane >> 2);
        int k0 = kt * 16 + 2 * (lane & 3);
        float f[4];
        #pragma unroll
        for (int j = 0; j < 4; ++j) {
            int k = k0 + (j >> 1) * 8 + (j & 1);
            f[j] = (n < 64) ? (Wk[(64 + k) * 64 + n] + Wq[(64 + k) * 64 + n])
                            : Wv[(64 + k) * 64 + (n - 64)];
        }
        uint32_t b0h, b0l, b1h, b1l;
        split2(f[0], f[1], b0h, b0l);
        split2(f[2], f[3], b1h, b1l);
        g_Bpack[s] = make_uint4(b0h, b1h, b0l, b1l);
    }
}

// ----------------------------------------------------------------------------
// Node kernel (R10 version: biases folded into kx and vx).
// ----------------------------------------------------------------------------
__global__ __launch_bounds__(256, 2) void node_kernel(
    const float* __restrict__ x,
    const float* __restrict__ Wk, const float* __restrict__ Wq,
    const float* __restrict__ Wv, const float* __restrict__ Wskip,
    const float* __restrict__ bk, const float* __restrict__ bq,
    const float* __restrict__ bv,
    const float* __restrict__ bias,
    float* __restrict__ out, int N)
{
    __shared__ float WA[64][64];
    __shared__ float WB[64][64];
    const int tid = threadIdx.x;
    const int part = blockIdx.y;
    const float* srcA = (part == 0) ? Wk : Wv;
    const float* srcB = (part == 0) ? Wq : Wskip;
    for (int i = tid; i < 4096; i += 256) {
        (&WA[0][0])[i] = srcA[i];
        (&WB[0][0])[i] = srcB[i];
    }
    __syncthreads();

    const int hw = tid >> 4;
    const int l  = tid & 15;
    const int base = blockIdx.x * 128;
    float* outA = (part == 0) ? g_kx : g_vx;

    for (int it = 0; it < 2; ++it) {
        int n[4]; bool valid[4];
        float2 a0[4], a1[4];
        #pragma unroll
        for (int j = 0; j < 4; ++j) {
            n[j] = base + it * 64 + j * 16 + hw;
            valid[j] = (n[j] < N);
            int nc = valid[j] ? n[j] : 0;
            const float2* xr = (const float2*)(x + (size_t)nc * 64);
            a0[j] = xr[l];
            a1[j] = xr[16 + l];
        }

        u64 accA0[4], accA1[4], accB0[4], accB1[4];
        #pragma unroll
        for (int j = 0; j < 4; ++j) { accA0[j]=0; accA1[j]=0; accB0[j]=0; accB1[j]=0; }

        #pragma unroll
        for (int p = 0; p < 16; ++p) {
            ulonglong2 wa0 = *(const ulonglong2*)&WA[2 * p][4 * l];
            ulonglong2 wa1 = *(const ulonglong2*)&WA[2 * p + 1][4 * l];
            ulonglong2 wb0 = *(const ulonglong2*)&WB[2 * p][4 * l];
            ulonglong2 wb1 = *(const ulonglong2*)&WB[2 * p + 1][4 * l];
            #pragma unroll
            for (int j = 0; j < 4; ++j) {
                float ax = __shfl_sync(0xffffffffu, a0[j].x, p, 16);
                float ay = __shfl_sync(0xffffffffu, a0[j].y, p, 16);
                u64 ax2 = pack2(ax, ax), ay2 = pack2(ay, ay);
                fma2(accA0[j], ax2, wa0.x); fma2(accA1[j], ax2, wa0.y);
                fma2(accA0[j], ay2, wa1.x); fma2(accA1[j], ay2, wa1.y);
                fma2(accB0[j], ax2, wb0.x); fma2(accB1[j], ax2, wb0.y);
                fma2(accB0[j], ay2, wb1.x); fma2(accB1[j], ay2, wb1.y);
            }
        }
        #pragma unroll
        for (int p = 0; p < 16; ++p) {
            ulonglong2 wa0 = *(const ulonglong2*)&WA[32 + 2 * p][4 * l];
            ulonglong2 wa1 = *(const ulonglong2*)&WA[33 + 2 * p][4 * l];
            ulonglong2 wb0 = *(const ulonglong2*)&WB[32 + 2 * p][4 * l];
            ulonglong2 wb1 = *(const ulonglong2*)&WB[33 + 2 * p][4 * l];
            #pragma unroll
            for (int j = 0; j < 4; ++j) {
                float ax = __shfl_sync(0xffffffffu, a1[j].x, p, 16);
                float ay = __shfl_sync(0xffffffffu, a1[j].y, p, 16);
                u64 ax2 = pack2(ax, ax), ay2 = pack2(ay, ay);
                fma2(accA0[j], ax2, wa0.x); fma2(accA1[j], ax2, wa0.y);
                fma2(accA0[j], ay2, wa1.x); fma2(accA1[j], ay2, wa1.y);
                fma2(accB0[j], ax2, wb0.x); fma2(accB1[j], ax2, wb0.y);
                fma2(accB0[j], ay2, wb1.x); fma2(accB1[j], ay2, wb1.y);
            }
        }

        #pragma unroll
        for (int j = 0; j < 4; ++j) {
            if (!valid[j]) continue;
            float4 rA, rB;
            unpack2(accA0[j], rA.x, rA.y); unpack2(accA1[j], rA.z, rA.w);
            unpack2(accB0[j], rB.x, rB.y); unpack2(accB1[j], rB.z, rB.w);
            if (part == 0) {
                float4 k4 = *(const float4*)(bk + 4 * l);
                float4 q4 = *(const float4*)(bq + 4 * l);
                rA.x += k4.x + q4.x; rA.y += k4.y + q4.y;
                rA.z += k4.z + q4.z; rA.w += k4.w + q4.w;
                *(float4*)(outA + (size_t)n[j] * 64 + 4 * l) = rA;
                *(float4*)(g_qx + (size_t)n[j] * 64 + 4 * l) = rB;
            } else {
                float4 v4 = *(const float4*)(bv + 4 * l);
                rA.x += v4.x; rA.y += v4.y; rA.z += v4.z; rA.w += v4.w;
                *(float4*)(outA + (size_t)n[j] * 64 + 4 * l) = rA;
                float4 b4 = *(const float4*)(bias + 4 * l);
                rB.x += b4.x; rB.y += b4.y; rB.z += b4.z; rB.w += b4.w;
                *(float4*)(out + (size_t)n[j] * 64 + 4 * l) = rB;
            }
        }
    }
}

// ----------------------------------------------------------------------------
// Edge kernel v10 (mma.sync): CTA 256 thr = 8 warps, tile 128 edges.
// Warp w: edges [tile*128 + 16w, +16). lane: g=lane>>2 (edge rows g, g+8),
// tig=lane&3 (col pairs 2tig, 2tig+1 per 8-col tile).
// A fragments built in registers (no smem); B fragment image in 16KB smem.
// D cols 0-63 = gate preact, 64-127 = value; drained per 8-col pair.
// ----------------------------------------------------------------------------
#define TILE_E 128

__global__ __launch_bounds__(256, 2) void edge_kernel(
    const float* __restrict__ ea,
    const int* __restrict__ srcArr, const int* __restrict__ dstArr,
    float* __restrict__ out, int E)
{
    __shared__ uint4 sB[1024];   // 16KB, mirrors g_Bpack

    const int tid  = threadIdx.x;
    const int w    = tid >> 5;
    const int lane = tid & 31;
    const int g    = lane >> 2;
    const int tig  = lane & 3;

    // Prologue: cp.async B fragment image.
    {
        unsigned sb = smem_u32(sB);
        #pragma unroll
        for (int i = 0; i < 4; ++i) {
            int idx = tid * 4 + i;
            asm volatile("cp.async.cg.shared.global [%0], [%1], 16;"
                         :: "r"(sb + idx * 16), "l"(g_Bpack + idx));
        }
        asm volatile("cp.async.commit_group;");
    }

    // A fragments: this thread needs rows e0=base+16w+g and e1=e0+8,
    // k pairs {2tig,2tig+1} and {+8,+9} per 16-k tile. Load + split to bf16.
    const long ebase = (long)blockIdx.x * TILE_E;
    long e0 = ebase + w * 16 + g;
    long e1 = e0 + 8;
    const bool v0 = (e0 < (long)E), v1 = (e1 < (long)E);
    const long e0c = v0 ? e0 : (long)E - 1;
    const long e1c = v1 ? e1 : (long)E - 1;

    uint32_t ah[2][4], al[2][4];
    #pragma unroll
    for (int kt = 0; kt < 2; ++kt) {
        const int k0 = kt * 16 + 2 * tig;
        float2 p0 = *(const float2*)(ea + e0c * 32 + k0);
        float2 p1 = *(const float2*)(ea + e1c * 32 + k0);
        float2 p2 = *(const float2*)(ea + e0c * 32 + k0 + 8);
        float2 p3 = *(const float2*)(ea + e1c * 32 + k0 + 8);
        split2(p0.x, p0.y, ah[kt][0], al[kt][0]);
        split2(p1.x, p1.y, ah[kt][1], al[kt][1]);
        split2(p2.x, p2.y, ah[kt][2], al[kt][2]);
        split2(p3.x, p3.y, ah[kt][3], al[kt][3]);
    }

    // Edge endpoints for the two rows this thread owns.
    const int dst0 = dstArr[e0c], src0 = srcArr[e0c];
    const int dst1 = dstArr[e1c], src1 = srcArr[e1c];
    const float* kx0 = g_kx + (size_t)dst0 * 64;
    const float* qx0 = g_qx + (size_t)src0 * 64;
    const float* vx0 = g_vx + (size_t)src0 * 64;
    const float* kx1 = g_kx + (size_t)dst1 * 64;
    const float* qx1 = g_qx + (size_t)src1 * 64;
    const float* vx1 = g_vx + (size_t)src1 * 64;
    float* o0 = out + (size_t)dst0 * 64;
    float* o1 = out + (size_t)dst1 * 64;

    asm volatile("cp.async.wait_group 0;");
    __syncthreads();

    #pragma unroll
    for (int p = 0; p < 8; ++p) {
        float cg[4] = {0.f, 0.f, 0.f, 0.f};
        float cv[4] = {0.f, 0.f, 0.f, 0.f};
        #pragma unroll
        for (int kt = 0; kt < 2; ++kt) {
            uint4 Bg = sB[(p * 2 + kt) * 32 + lane];        // gate ntile p
            uint4 Bv = sB[((p + 8) * 2 + kt) * 32 + lane];  // value ntile p+8
            mma_bf16(cg, ah[kt], Bg.x, Bg.y);   // hi * hi
            mma_bf16(cg, ah[kt], Bg.z, Bg.w);   // hi * lo
            mma_bf16(cg, al[kt], Bg.x, Bg.y);   // lo * hi
            mma_bf16(cv, ah[kt], Bv.x, Bv.y);
            mma_bf16(cv, ah[kt], Bv.z, Bv.w);
            mma_bf16(cv, al[kt], Bv.x, Bv.y);
        }
        // Drain: thread owns (rows g,g+8) x (cols c0,c0+1) of this 8-col block.
        const int c0 = 8 * p + 2 * tig;
        float2 kd0 = *(const float2*)(kx0 + c0);
        float2 qs0 = *(const float2*)(qx0 + c0);
        float2 vs0 = *(const float2*)(vx0 + c0);
        float2 kd1 = *(const float2*)(kx1 + c0);
        float2 qs1 = *(const float2*)(qx1 + c0);
        float2 vs1 = *(const float2*)(vx1 + c0);
        float m00 = fast_sigmoid(cg[0] + kd0.x + qs0.x) * (cv[0] + vs0.x);
        float m01 = fast_sigmoid(cg[1] + kd0.y + qs0.y) * (cv[1] + vs0.y);
        float m10 = fast_sigmoid(cg[2] + kd1.x + qs1.x) * (cv[2] + vs1.x);
        float m11 = fast_sigmoid(cg[3] + kd1.y + qs1.y) * (cv[3] + vs1.y);
        if (v0)
            asm volatile("red.global.add.v2.f32 [%0], {%1,%2};"
                         :: "l"(o0 + c0), "f"(m00), "f"(m01) : "memory");
        if (v1)
            asm volatile("red.global.add.v2.f32 [%0], {%1,%2};"
                         :: "l"(o1 + c0), "f"(m10), "f"(m11) : "memory");
    }
}

// ----------------------------------------------------------------------------
// Launch. Inputs: x, edge_index, edge_attr, Wk, bk, Wq, bq, Wv, bv, Wskip, bias.
// ----------------------------------------------------------------------------
extern "C" void kernel_launch(void* const* d_in, const int* in_sizes, int n_in,
                              void* d_out, int out_size)
{
    const float* x     = (const float*)d_in[0];
    const int*   ei    = (const int*)d_in[1];
    const float* ea    = (const float*)d_in[2];
    const float* Wk    = (const float*)d_in[3];
    const float* bk    = (const float*)d_in[4];
    const float* Wq    = (const float*)d_in[5];
    const float* bq    = (const float*)d_in[6];
    const float* Wv    = (const float*)d_in[7];
    const float* bv    = (const float*)d_in[8];
    const float* Wskip = (const float*)d_in[9];
    const float* bias  = (const float*)d_in[10];
    float* out = (float*)d_out;

    int N = in_sizes[0] / 64;   // x is [N, 64]
    int E = in_sizes[2] / 32;   // edge_attr is [E, 32]

    dim3 ngrid((N + 127) / 128, 2);
    node_kernel<<<ngrid, 256>>>(x, Wk, Wq, Wv, Wskip, bk, bq, bv, bias, out, N);

    bpack_kernel<<<1, 256>>>(Wk, Wq, Wv);

    int numTiles = (E + TILE_E - 1) / TILE_E;
    edge_kernel<<<numTiles, 256>>>(ea, ei, ei + E, out, E);
}

// round 12
// speedup vs baseline: 2.0090x; 1.1218x over previous
#include <cuda_runtime.h>
#include <cuda_bf16.h>
#include <cstdint>

// ============================================================================
// EdgeAggregatorGATED round 12: both GEMMs on tensor cores (mma.sync bf16
// split hi/lo, 3 products). Edge kernel = validated R11 version. Node kernel
// rewritten in the same fragment structure: A(x rows) register-direct, B
// ([Wk|Wq|Wv|Wskip] node parts) pre-packed to fragment layout, epilogue STG
// with folded biases. bpack packs both weight images in one launch.
// ============================================================================

#define MAXN 51200
__device__ float g_kx[MAXN * 64];
__device__ float g_qx[MAXN * 64];
__device__ float g_vx[MAXN * 64];
__device__ uint4 g_Bpack[1024];    // edge B image, 16KB
__device__ uint4 g_BpackN[4096];   // node B image, 64KB (two 32KB halves)

__device__ __forceinline__ float fast_sigmoid(float s) {
    return __fdividef(1.0f, 1.0f + __expf(-s));
}
__device__ __forceinline__ unsigned smem_u32(const void* p) {
    return (unsigned)__cvta_generic_to_shared(p);
}
__device__ __forceinline__ uint32_t bf2(float a, float b) {
    uint32_t r; asm("cvt.rn.bf16x2.f32 %0, %1, %2;" : "=r"(r) : "f"(b), "f"(a));
    return r;
}
__device__ __forceinline__ float2 bf2_back(uint32_t h) {
    return make_float2(__uint_as_float(h << 16), __uint_as_float(h & 0xffff0000u));
}
__device__ __forceinline__ void split2(float a, float b, uint32_t& hi, uint32_t& lo) {
    hi = bf2(a, b);
    float2 hb = bf2_back(hi);
    lo = bf2(a - hb.x, b - hb.y);
}
__device__ __forceinline__ void mma_bf16(float c[4], const uint32_t a[4],
                                         uint32_t b0, uint32_t b1) {
    asm volatile(
        "mma.sync.aligned.m16n8k16.row.col.f32.bf16.bf16.f32 "
        "{%0,%1,%2,%3}, {%4,%5,%6,%7}, {%8,%9}, {%0,%1,%2,%3};"
        : "+f"(c[0]), "+f"(c[1]), "+f"(c[2]), "+f"(c[3])
        : "r"(a[0]), "r"(a[1]), "r"(a[2]), "r"(a[3]), "r"(b0), "r"(b1));
}

// ----------------------------------------------------------------------------
// bpack (one launch, 3 blocks x 256):
//   block 0: edge B  [n=128][k=32] from Wk/Wq/Wv edge rows (64..95)
//   blocks 1,2: node B [n=256][k=64]; n: 0-63 kx(Wk), 64-127 qx(Wq),
//               128-191 vx(Wv), 192-255 skip(Wskip). Rows 0..63 of each W.
// slot layout (both): s = (ntile*KT + kt)*32 + lane;
//   n = ntile*8 + (lane>>2), k0 = kt*16 + 2*(lane&3);
//   uint4 = {b0h, b1h, b0l, b1l} for k pairs {k0,k0+1} and {k0+8,k0+9}.
// ----------------------------------------------------------------------------
__global__ void bpack_kernel(const float* __restrict__ Wk,
                             const float* __restrict__ Wq,
                             const float* __restrict__ Wv,
                             const float* __restrict__ Wskip)
{
    int t = threadIdx.x;
    if (blockIdx.x == 0) {
        #pragma unroll
        for (int i = 0; i < 4; ++i) {
            int s = t * 4 + i;
            int nt = s >> 6;
            int kt = (s >> 5) & 1;
            int lane = s & 31;
            int n = nt * 8 + (lane >> 2);
            int k0 = kt * 16 + 2 * (lane & 3);
            float f[4];
            #pragma unroll
            for (int j = 0; j < 4; ++j) {
                int k = k0 + (j >> 1) * 8 + (j & 1);
                f[j] = (n < 64) ? (Wk[(64 + k) * 64 + n] + Wq[(64 + k) * 64 + n])
                                : Wv[(64 + k) * 64 + (n - 64)];
            }
            uint32_t b0h, b0l, b1h, b1l;
            split2(f[0], f[1], b0h, b0l);
            split2(f[2], f[3], b1h, b1l);
            g_Bpack[s] = make_uint4(b0h, b1h, b0l, b1l);
        }
    } else {
        int base = (blockIdx.x - 1) * 2048;
        #pragma unroll
        for (int i = 0; i < 8; ++i) {
            int s = base + t * 8 + i;
            int nt = s >> 7;          // 0..31
            int kt = (s >> 5) & 3;    // 0..3
            int lane = s & 31;
            int n = nt * 8 + (lane >> 2);   // 0..255
            int k0 = kt * 16 + 2 * (lane & 3);
            const float* W = (n < 64) ? Wk : (n < 128) ? Wq : (n < 192) ? Wv : Wskip;
            int nc = n & 63;
            float f[4];
            #pragma unroll
            for (int j = 0; j < 4; ++j) {
                int k = k0 + (j >> 1) * 8 + (j & 1);
                f[j] = W[k * 64 + nc];
            }
            uint32_t b0h, b0l, b1h, b1l;
            split2(f[0], f[1], b0h, b0l);
            split2(f[2], f[3], b1h, b1l);
            g_BpackN[s] = make_uint4(b0h, b1h, b0l, b1l);
        }
    }
}

// ----------------------------------------------------------------------------
// Node kernel v2 (mma.sync): CTA 256 thr, tile 128 nodes x 128 cols,
// blockIdx.y = col half (0: kx|qx, 1: vx|skip->out).
// ----------------------------------------------------------------------------
__global__ __launch_bounds__(256, 2) void node_kernel(
    const float* __restrict__ x,
    const float* __restrict__ bk, const float* __restrict__ bq,
    const float* __restrict__ bv, const float* __restrict__ bias,
    float* __restrict__ out, int N)
{
    __shared__ uint4 sB[2048];   // 32KB: one 128-col half of g_BpackN

    const int tid  = threadIdx.x;
    const int w    = tid >> 5;
    const int lane = tid & 31;
    const int g    = lane >> 2;
    const int tig  = lane & 3;
    const int half = blockIdx.y;

    {
        unsigned sb = smem_u32(sB);
        const uint4* src = g_BpackN + half * 2048;
        #pragma unroll
        for (int i = 0; i < 8; ++i) {
            int idx = tid * 8 + i;
            asm volatile("cp.async.cg.shared.global [%0], [%1], 16;"
                         :: "r"(sb + idx * 16), "l"(src + idx));
        }
        asm volatile("cp.async.commit_group;");
    }

    // A fragments from x: rows n0, n1 = n0+8; 4 k-tiles.
    const int nbase = blockIdx.x * 128;
    int n0 = nbase + w * 16 + g;
    int n1 = n0 + 8;
    const bool v0 = (n0 < N), v1 = (n1 < N);
    const int n0c = v0 ? n0 : N - 1;
    const int n1c = v1 ? n1 : N - 1;

    uint32_t ah[4][4], al[4][4];
    #pragma unroll
    for (int kt = 0; kt < 4; ++kt) {
        const int k0 = kt * 16 + 2 * tig;
        float2 p0 = *(const float2*)(x + (size_t)n0c * 64 + k0);
        float2 p1 = *(const float2*)(x + (size_t)n1c * 64 + k0);
        float2 p2 = *(const float2*)(x + (size_t)n0c * 64 + k0 + 8);
        float2 p3 = *(const float2*)(x + (size_t)n1c * 64 + k0 + 8);
        split2(p0.x, p0.y, ah[kt][0], al[kt][0]);
        split2(p1.x, p1.y, ah[kt][1], al[kt][1]);
        split2(p2.x, p2.y, ah[kt][2], al[kt][2]);
        split2(p3.x, p3.y, ah[kt][3], al[kt][3]);
    }

    asm volatile("cp.async.wait_group 0;");
    __syncthreads();

    #pragma unroll
    for (int p = 0; p < 16; ++p) {
        float c[4] = {0.f, 0.f, 0.f, 0.f};
        #pragma unroll
        for (int kt = 0; kt < 4; ++kt) {
            uint4 B = sB[(p * 4 + kt) * 32 + lane];
            mma_bf16(c, ah[kt], B.x, B.y);   // hi*hi
            mma_bf16(c, ah[kt], B.z, B.w);   // hi*lo
            mma_bf16(c, al[kt], B.x, B.y);   // lo*hi
        }
        const int cc = 8 * p + 2 * tig;   // 0..127 within this half
        float2 badd = make_float2(0.f, 0.f);
        float* table;
        int col;
        if (half == 0) {
            if (p < 8) {  // kx, bias bk+bq
                table = g_kx; col = cc;
                float2 a = *(const float2*)(bk + col);
                float2 b = *(const float2*)(bq + col);
                badd = make_float2(a.x + b.x, a.y + b.y);
            } else {      // qx, no bias
                table = g_qx; col = cc - 64;
            }
        } else {
            if (p < 8) {  // vx, bias bv
                table = g_vx; col = cc;
                badd = *(const float2*)(bv + col);
            } else {      // out = skip + bias
                table = out; col = cc - 64;
                badd = *(const float2*)(bias + col);
            }
        }
        if (v0) *(float2*)(table + (size_t)n0 * 64 + col) =
            make_float2(c[0] + badd.x, c[1] + badd.y);
        if (v1) *(float2*)(table + (size_t)n1 * 64 + col) =
            make_float2(c[2] + badd.x, c[3] + badd.y);
    }
}

// ----------------------------------------------------------------------------
// Edge kernel (validated R11): CTA 256 thr, tile 128 edges; A register-direct,
// B fragment image in smem; drain per 8-col pair; RED.64 scatter.
// ----------------------------------------------------------------------------
#define TILE_E 128

__global__ __launch_bounds__(256, 2) void edge_kernel(
    const float* __restrict__ ea,
    const int* __restrict__ srcArr, const int* __restrict__ dstArr,
    float* __restrict__ out, int E)
{
    __shared__ uint4 sB[1024];   // 16KB

    const int tid  = threadIdx.x;
    const int w    = tid >> 5;
    const int lane = tid & 31;
    const int g    = lane >> 2;
    const int tig  = lane & 3;

    {
        unsigned sb = smem_u32(sB);
        #pragma unroll
        for (int i = 0; i < 4; ++i) {
            int idx = tid * 4 + i;
            asm volatile("cp.async.cg.shared.global [%0], [%1], 16;"
                         :: "r"(sb + idx * 16), "l"(g_Bpack + idx));
        }
        asm volatile("cp.async.commit_group;");
    }

    const long ebase = (long)blockIdx.x * TILE_E;
    long e0 = ebase + w * 16 + g;
    long e1 = e0 + 8;
    const bool v0 = (e0 < (long)E), v1 = (e1 < (long)E);
    const long e0c = v0 ? e0 : (long)E - 1;
    const long e1c = v1 ? e1 : (long)E - 1;

    uint32_t ah[2][4], al[2][4];
    #pragma unroll
    for (int kt = 0; kt < 2; ++kt) {
        const int k0 = kt * 16 + 2 * tig;
        float2 p0 = *(const float2*)(ea + e0c * 32 + k0);
        float2 p1 = *(const float2*)(ea + e1c * 32 + k0);
        float2 p2 = *(const float2*)(ea + e0c * 32 + k0 + 8);
        float2 p3 = *(const float2*)(ea + e1c * 32 + k0 + 8);
        split2(p0.x, p0.y, ah[kt][0], al[kt][0]);
        split2(p1.x, p1.y, ah[kt][1], al[kt][1]);
        split2(p2.x, p2.y, ah[kt][2], al[kt][2]);
        split2(p3.x, p3.y, ah[kt][3], al[kt][3]);
    }

    const int dst0 = dstArr[e0c], src0 = srcArr[e0c];
    const int dst1 = dstArr[e1c], src1 = srcArr[e1c];
    const float* kx0 = g_kx + (size_t)dst0 * 64;
    const float* qx0 = g_qx + (size_t)src0 * 64;
    const float* vx0 = g_vx + (size_t)src0 * 64;
    const float* kx1 = g_kx + (size_t)dst1 * 64;
    const float* qx1 = g_qx + (size_t)src1 * 64;
    const float* vx1 = g_vx + (size_t)src1 * 64;
    float* o0 = out + (size_t)dst0 * 64;
    float* o1 = out + (size_t)dst1 * 64;

    asm volatile("cp.async.wait_group 0;");
    __syncthreads();

    #pragma unroll
    for (int p = 0; p < 8; ++p) {
        float cg[4] = {0.f, 0.f, 0.f, 0.f};
        float cv[4] = {0.f, 0.f, 0.f, 0.f};
        #pragma unroll
        for (int kt = 0; kt < 2; ++kt) {
            uint4 Bg = sB[(p * 2 + kt) * 32 + lane];
            uint4 Bv = sB[((p + 8) * 2 + kt) * 32 + lane];
            mma_bf16(cg, ah[kt], Bg.x, Bg.y);
            mma_bf16(cg, ah[kt], Bg.z, Bg.w);
            mma_bf16(cg, al[kt], Bg.x, Bg.y);
            mma_bf16(cv, ah[kt], Bv.x, Bv.y);
            mma_bf16(cv, ah[kt], Bv.z, Bv.w);
            mma_bf16(cv, al[kt], Bv.x, Bv.y);
        }
        const int c0 = 8 * p + 2 * tig;
        float2 kd0 = *(const float2*)(kx0 + c0);
        float2 qs0 = *(const float2*)(qx0 + c0);
        float2 vs0 = *(const float2*)(vx0 + c0);
        float2 kd1 = *(const float2*)(kx1 + c0);
        float2 qs1 = *(const float2*)(qx1 + c0);
        float2 vs1 = *(const float2*)(vx1 + c0);
        float m00 = fast_sigmoid(cg[0] + kd0.x + qs0.x) * (cv[0] + vs0.x);
        float m01 = fast_sigmoid(cg[1] + kd0.y + qs0.y) * (cv[1] + vs0.y);
        float m10 = fast_sigmoid(cg[2] + kd1.x + qs1.x) * (cv[2] + vs1.x);
        float m11 = fast_sigmoid(cg[3] + kd1.y + qs1.y) * (cv[3] + vs1.y);
        if (v0)
            asm volatile("red.global.add.v2.f32 [%0], {%1,%2};"
                         :: "l"(o0 + c0), "f"(m00), "f"(m01) : "memory");
        if (v1)
            asm volatile("red.global.add.v2.f32 [%0], {%1,%2};"
                         :: "l"(o1 + c0), "f"(m10), "f"(m11) : "memory");
    }
}

// ----------------------------------------------------------------------------
// Launch. Inputs: x, edge_index, edge_attr, Wk, bk, Wq, bq, Wv, bv, Wskip, bias.
// ----------------------------------------------------------------------------
extern "C" void kernel_launch(void* const* d_in, const int* in_sizes, int n_in,
                              void* d_out, int out_size)
{
    const float* x     = (const float*)d_in[0];
    const int*   ei    = (const int*)d_in[1];
    const float* ea    = (const float*)d_in[2];
    const float* Wk    = (const float*)d_in[3];
    const float* bk    = (const float*)d_in[4];
    const float* Wq    = (const float*)d_in[5];
    const float* bq    = (const float*)d_in[6];
    const float* Wv    = (const float*)d_in[7];
    const float* bv    = (const float*)d_in[8];
    const float* Wskip = (const float*)d_in[9];
    const float* bias  = (const float*)d_in[10];
    float* out = (float*)d_out;

    int N = in_sizes[0] / 64;   // x is [N, 64]
    int E = in_sizes[2] / 32;   // edge_attr is [E, 32]

    bpack_kernel<<<3, 256>>>(Wk, Wq, Wv, Wskip);

    dim3 ngrid((N + 127) / 128, 2);
    node_kernel<<<ngrid, 256>>>(x, bk, bq, bv, bias, out, N);

    int numTiles = (E + TILE_E - 1) / TILE_E;
    edge_kernel<<<numTiles, 256>>>(ea, ei, ei + E, out, E);
}